// round 10
// baseline (speedup 1.0000x reference)
#include <cuda_runtime.h>
#include <math.h>
#include <stdint.h>

// ---------------- scratch (static device globals; no allocation) ----------------
__device__ float    g_q  [(size_t)4 * 4096 * 256];   // [b][n][oc]      tf32 bits
__device__ uint32_t g_kp [(size_t)4 * 8 * 1024 * 32];// [b][h][m][32]   K tf32, frag-perm
__device__ uint32_t g_vp [(size_t)4 * 8 * 1024 * 32];// [b][h][m][32]   V tf32, frag-perm
__device__ float    g_vt [(size_t)4 * 256 * 1024];   // [b][c][m]       fp32 planar v
__device__ float    g_vpe[(size_t)4 * 1024 * 256];   // [b][m][c]
__device__ float    g_pre[(size_t)4 * 4096 * 256];   // [b][n][c]

// ---------------- tf32 helpers ----------------
__device__ __forceinline__ uint32_t f2tf(float f) {
    uint32_t r; asm("cvt.rna.tf32.f32 %0, %1;" : "=r"(r) : "f"(f)); return r;
}
__device__ __forceinline__ void mma_tf32(float c[4], const uint32_t a[4],
                                         uint32_t b0, uint32_t b1) {
    asm("mma.sync.aligned.m16n8k8.row.col.f32.tf32.tf32.f32 "
        "{%0,%1,%2,%3}, {%4,%5,%6,%7}, {%8,%9}, {%0,%1,%2,%3};"
        : "+f"(c[0]), "+f"(c[1]), "+f"(c[2]), "+f"(c[3])
        : "r"(a[0]), "r"(a[1]), "r"(a[2]), "r"(a[3]), "r"(b0), "r"(b1));
}

// =================================================================================
// tf32 conv1x1, input planar [C][Nsp], output n-major [Nsp][O], pipelined loads.
// kv mode (kp!=nullptr): writes K/V into fragment-permuted tf32 buffers + fp32
// planar v (no n-major output). q mode: writes tf32-bit n-major output.
// =================================================================================
__global__ __launch_bounds__(256) void k_conv_tf32_nmajor(
    const float* __restrict__ X, const float* __restrict__ W,
    const float* __restrict__ scale, const float* __restrict__ bias,
    float* __restrict__ out, uint32_t* __restrict__ kp, uint32_t* __restrict__ vp,
    float* __restrict__ vt, int C, int Nsp, int O)
{
    __shared__ __align__(16) uint32_t As[32 * 136];
    __shared__ __align__(16) uint32_t Ws[64 * 36];
    const int b  = blockIdx.z;
    const int n0 = blockIdx.y * 128;
    const int o0 = blockIdx.x * 64;
    const int tid = threadIdx.x;
    const int warp = tid >> 5, lane = tid & 31;
    const int gid = lane >> 2, tig = lane & 3;
    const int wm = warp * 16;

    const float* Xb = X + (size_t)b * C * Nsp;
    float Cacc[8][4];
    #pragma unroll
    for (int i = 0; i < 8; i++)
        #pragma unroll
        for (int j = 0; j < 4; j++) Cacc[i][j] = 0.0f;

    float4 ra[4], rb[2];
    #pragma unroll
    for (int i = 0; i < 4; i++) {
        int idx = tid + 256 * i;
        int k = idx >> 5, mq = (idx & 31) * 4;
        ra[i] = *(const float4*)&Xb[(size_t)k * Nsp + n0 + mq];
    }
    #pragma unroll
    for (int i = 0; i < 2; i++) {
        int idx = tid + 256 * i;
        int o = idx >> 3, kq = (idx & 7) * 4;
        rb[i] = *(const float4*)&W[(size_t)(o0 + o) * C + kq];
    }

    for (int c0 = 0; c0 < C; c0 += 32) {
        #pragma unroll
        for (int i = 0; i < 4; i++) {
            int idx = tid + 256 * i;
            int k = idx >> 5, mq = (idx & 31) * 4;
            uint4 u; u.x = f2tf(ra[i].x); u.y = f2tf(ra[i].y);
                     u.z = f2tf(ra[i].z); u.w = f2tf(ra[i].w);
            *(uint4*)&As[k * 136 + mq] = u;
        }
        #pragma unroll
        for (int i = 0; i < 2; i++) {
            int idx = tid + 256 * i;
            int o = idx >> 3, kq = (idx & 7) * 4;
            uint4 u; u.x = f2tf(rb[i].x); u.y = f2tf(rb[i].y);
                     u.z = f2tf(rb[i].z); u.w = f2tf(rb[i].w);
            *(uint4*)&Ws[o * 36 + kq] = u;
        }
        __syncthreads();
        if (c0 + 32 < C) {
            #pragma unroll
            for (int i = 0; i < 4; i++) {
                int idx = tid + 256 * i;
                int k = idx >> 5, mq = (idx & 31) * 4;
                ra[i] = *(const float4*)&Xb[(size_t)(c0 + 32 + k) * Nsp + n0 + mq];
            }
            #pragma unroll
            for (int i = 0; i < 2; i++) {
                int idx = tid + 256 * i;
                int o = idx >> 3, kq = (idx & 7) * 4;
                rb[i] = *(const float4*)&W[(size_t)(o0 + o) * C + c0 + 32 + kq];
            }
        }
        #pragma unroll
        for (int ks = 0; ks < 4; ks++) {
            int kk = ks * 8 + tig;
            uint32_t aF[4];
            aF[0] = As[kk * 136 + wm + gid];
            aF[1] = As[kk * 136 + wm + gid + 8];
            aF[2] = As[(kk + 4) * 136 + wm + gid];
            aF[3] = As[(kk + 4) * 136 + wm + gid + 8];
            #pragma unroll
            for (int nt = 0; nt < 8; nt++) {
                uint32_t b0 = Ws[(nt * 8 + gid) * 36 + kk];
                uint32_t b1 = Ws[(nt * 8 + gid) * 36 + kk + 4];
                mma_tf32(Cacc[nt], aF, b0, b1);
            }
        }
        __syncthreads();
    }

    const int nlo = n0 + wm + gid, nhi = nlo + 8;
    #pragma unroll
    for (int nt = 0; nt < 8; nt++) {
        int o = o0 + nt * 8 + 2 * tig;          // even
        float2 sc = *(const float2*)&scale[o];
        float2 bi = *(const float2*)&bias[o];
        float2 lo, hi;
        lo.x = Cacc[nt][0] * sc.x + bi.x;
        lo.y = Cacc[nt][1] * sc.y + bi.y;
        hi.x = Cacc[nt][2] * sc.x + bi.x;
        hi.y = Cacc[nt][3] * sc.y + bi.y;

        if (kp != nullptr) {
            // kv mode: fragment-permuted K/V tf32 buffers (+ fp32 planar v)
            int h = o >> 6;
            int c = o & 63;
            size_t base = ((size_t)b * 8 + h) * 1024;
            if (c < 32) {
                int p0 = (c & 3) * 8 + (c >> 2);
                int p1 = ((c + 1) & 3) * 8 + ((c + 1) >> 2);
                kp[(base + nlo) * 32 + p0] = f2tf(lo.x);
                kp[(base + nlo) * 32 + p1] = f2tf(lo.y);
                kp[(base + nhi) * 32 + p0] = f2tf(hi.x);
                kp[(base + nhi) * 32 + p1] = f2tf(hi.y);
            } else {
                int cv = c - 32;
                int p0 = (cv & 7) * 4 + (cv >> 3);
                int p1 = ((cv + 1) & 7) * 4 + ((cv + 1) >> 3);
                vp[(base + nlo) * 32 + p0] = f2tf(lo.x);
                vp[(base + nlo) * 32 + p1] = f2tf(lo.y);
                vp[(base + nhi) * 32 + p0] = f2tf(hi.x);
                vp[(base + nhi) * 32 + p1] = f2tf(hi.y);
                int vc = h * 32 + cv;
                vt[((size_t)b * 256 + vc)     * Nsp + nlo] = lo.x;
                vt[((size_t)b * 256 + vc + 1) * Nsp + nlo] = lo.y;
                vt[((size_t)b * 256 + vc)     * Nsp + nhi] = hi.x;
                vt[((size_t)b * 256 + vc + 1) * Nsp + nhi] = hi.y;
            }
        } else {
            // q mode: tf32 bit pattern, n-major
            lo.x = __uint_as_float(f2tf(lo.x));
            lo.y = __uint_as_float(f2tf(lo.y));
            hi.x = __uint_as_float(f2tf(hi.x));
            hi.y = __uint_as_float(f2tf(hi.y));
            *(float2*)&out[((size_t)b * Nsp + nlo) * O + o] = lo;
            *(float2*)&out[((size_t)b * Nsp + nhi) * O + o] = hi;
        }
    }
}

// =================================================================================
// tf32 conv1x1 projection: input row-major [Nsp][C], output planar [O][Nsp]
// =================================================================================
__global__ __launch_bounds__(256) void k_conv_tf32_proj(
    const float* __restrict__ Ain, const float* __restrict__ W,
    const float* __restrict__ scale, const float* __restrict__ bias,
    float* __restrict__ out, int C, int Nsp, int O)
{
    __shared__ __align__(16) uint32_t Wa[128 * 36];
    __shared__ __align__(16) uint32_t Ab[64 * 36];
    const int b  = blockIdx.z;
    const int o0 = blockIdx.x * 128;
    const int n0 = blockIdx.y * 64;
    const int tid = threadIdx.x;
    const int warp = tid >> 5, lane = tid & 31;
    const int gid = lane >> 2, tig = lane & 3;
    const int wm = warp * 16;

    const float* Ainb = Ain + (size_t)b * Nsp * C;
    float Cacc[8][4];
    #pragma unroll
    for (int i = 0; i < 8; i++)
        #pragma unroll
        for (int j = 0; j < 4; j++) Cacc[i][j] = 0.0f;

    float4 ra[4], rb[2];
    #pragma unroll
    for (int i = 0; i < 4; i++) {
        int idx = tid + 256 * i;
        int o = idx >> 3, kq = (idx & 7) * 4;
        ra[i] = *(const float4*)&W[(size_t)(o0 + o) * C + kq];
    }
    #pragma unroll
    for (int i = 0; i < 2; i++) {
        int idx = tid + 256 * i;
        int n = idx >> 3, kq = (idx & 7) * 4;
        rb[i] = *(const float4*)&Ainb[(size_t)(n0 + n) * C + kq];
    }

    for (int c0 = 0; c0 < C; c0 += 32) {
        #pragma unroll
        for (int i = 0; i < 4; i++) {
            int idx = tid + 256 * i;
            int o = idx >> 3, kq = (idx & 7) * 4;
            uint4 u; u.x = f2tf(ra[i].x); u.y = f2tf(ra[i].y);
                     u.z = f2tf(ra[i].z); u.w = f2tf(ra[i].w);
            *(uint4*)&Wa[o * 36 + kq] = u;
        }
        #pragma unroll
        for (int i = 0; i < 2; i++) {
            int idx = tid + 256 * i;
            int n = idx >> 3, kq = (idx & 7) * 4;
            uint4 u; u.x = f2tf(rb[i].x); u.y = f2tf(rb[i].y);
                     u.z = f2tf(rb[i].z); u.w = f2tf(rb[i].w);
            *(uint4*)&Ab[n * 36 + kq] = u;
        }
        __syncthreads();
        if (c0 + 32 < C) {
            #pragma unroll
            for (int i = 0; i < 4; i++) {
                int idx = tid + 256 * i;
                int o = idx >> 3, kq = (idx & 7) * 4;
                ra[i] = *(const float4*)&W[(size_t)(o0 + o) * C + c0 + 32 + kq];
            }
            #pragma unroll
            for (int i = 0; i < 2; i++) {
                int idx = tid + 256 * i;
                int n = idx >> 3, kq = (idx & 7) * 4;
                rb[i] = *(const float4*)&Ainb[(size_t)(n0 + n) * C + c0 + 32 + kq];
            }
        }
        #pragma unroll
        for (int ks = 0; ks < 4; ks++) {
            int kk = ks * 8 + tig;
            uint32_t aF[4];
            aF[0] = Wa[(wm + gid) * 36 + kk];
            aF[1] = Wa[(wm + gid + 8) * 36 + kk];
            aF[2] = Wa[(wm + gid) * 36 + kk + 4];
            aF[3] = Wa[(wm + gid + 8) * 36 + kk + 4];
            #pragma unroll
            for (int nt = 0; nt < 8; nt++) {
                uint32_t b0 = Ab[(nt * 8 + gid) * 36 + kk];
                uint32_t b1 = Ab[(nt * 8 + gid) * 36 + kk + 4];
                mma_tf32(Cacc[nt], aF, b0, b1);
            }
        }
        __syncthreads();
    }

    const int olo = o0 + wm + gid, ohi = olo + 8;
    const float sclo = scale[olo], bilo = bias[olo];
    const float schi = scale[ohi], bihi = bias[ohi];
    #pragma unroll
    for (int nt = 0; nt < 8; nt++) {
        int n = n0 + nt * 8 + 2 * tig;
        float2 lo, hi;
        lo.x = Cacc[nt][0] * sclo + bilo;
        lo.y = Cacc[nt][1] * sclo + bilo;
        hi.x = Cacc[nt][2] * schi + bihi;
        hi.y = Cacc[nt][3] * schi + bihi;
        *(float2*)&out[((size_t)b * O + olo) * Nsp + n] = lo;
        *(float2*)&out[((size_t)b * O + ohi) * Nsp + n] = hi;
    }
}

// =================================================================================
// attention v4: K/V pre-permuted into fragment order -> 2 LDS.128 per QK/AV step,
// zero address swizzle math. cp.async double buffer, shuffle P exchange.
// smem pool: [Ks0 | Ks1 | Vs0 | Vs1] = [2x 64*36 | 2x 64*40] words.
// =================================================================================
#define KS_OFF(buf) ((buf) * 2304)
#define VS_OFF(buf) (4608 + (buf) * 2560)

__global__ __launch_bounds__(256) void k_attn_mma3(
    const uint32_t* __restrict__ q, const uint32_t* __restrict__ kp,
    const uint32_t* __restrict__ vp, float* __restrict__ pre)
{
    __shared__ __align__(16) uint32_t pool[9728];   // 38 KB

    const int bh = blockIdx.y;
    const int b = bh >> 3, h = bh & 7;
    const int tid = threadIdx.x;
    const int warp = tid >> 5, lane = tid & 31;
    const int gid = lane >> 2, tig = lane & 3;
    const int n0 = blockIdx.x * 128;

    // ---- stage q tile [128][32] (stride 33) and build A-frags ----
    #pragma unroll
    for (int i = 0; i < 4; i++) {
        int idx = tid + 256 * i;               // 0..1023
        int r = idx >> 3, v4 = (idx & 7) * 4;
        uint4 t = *(const uint4*)&q[((size_t)b * 4096 + n0 + r) * 256 + h * 32 + v4];
        pool[r * 33 + v4 + 0] = t.x;
        pool[r * 33 + v4 + 1] = t.y;
        pool[r * 33 + v4 + 2] = t.z;
        pool[r * 33 + v4 + 3] = t.w;
    }
    __syncthreads();

    uint32_t qA[4][4];
    {
        int r0 = warp * 16 + gid;
        #pragma unroll
        for (int ks = 0; ks < 4; ks++) {
            int c = ks * 8 + tig;
            qA[ks][0] = pool[r0 * 33 + c];
            qA[ks][1] = pool[(r0 + 8) * 33 + c];
            qA[ks][2] = pool[r0 * 33 + c + 4];
            qA[ks][3] = pool[(r0 + 8) * 33 + c + 4];
        }
    }
    __syncthreads();

    const uint32_t* kpb = kp + ((size_t)b * 8 + h) * 1024 * 32;
    const uint32_t* vpb = vp + ((size_t)b * 8 + h) * 1024 * 32;

    // prefetch chunk 0
    #pragma unroll
    for (int ii = 0; ii < 2; ii++) {
        int idx = tid + 256 * ii;              // 0..511
        int r = idx >> 3, jc = (idx & 7) * 4;
        uint32_t dK = (uint32_t)__cvta_generic_to_shared(&pool[KS_OFF(0) + r * 36 + jc]);
        const uint32_t* sK = &kpb[(size_t)r * 32 + jc];
        asm volatile("cp.async.cg.shared.global [%0], [%1], 16;" :: "r"(dK), "l"(sK));
        uint32_t dV = (uint32_t)__cvta_generic_to_shared(&pool[VS_OFF(0) + r * 40 + jc]);
        const uint32_t* sV = &vpb[(size_t)r * 32 + jc];
        asm volatile("cp.async.cg.shared.global [%0], [%1], 16;" :: "r"(dV), "l"(sV));
    }
    asm volatile("cp.async.commit_group;" ::: "memory");

    float O[4][4];
    #pragma unroll
    for (int i = 0; i < 4; i++)
        #pragma unroll
        for (int j = 0; j < 4; j++) O[i][j] = 0.0f;
    float l_lo = 0.0f, l_hi = 0.0f;
    const float SCL = 0.17677669529663687f;    // 1/sqrt(32)

    for (int ci = 0; ci < 16; ci++) {
        const int cur = ci & 1;
        if (ci < 15) {
            #pragma unroll
            for (int ii = 0; ii < 2; ii++) {
                int idx = tid + 256 * ii;
                int r = idx >> 3, jc = (idx & 7) * 4;
                uint32_t dK = (uint32_t)__cvta_generic_to_shared(&pool[KS_OFF(cur ^ 1) + r * 36 + jc]);
                const uint32_t* sK = &kpb[(size_t)((ci + 1) * 64 + r) * 32 + jc];
                asm volatile("cp.async.cg.shared.global [%0], [%1], 16;" :: "r"(dK), "l"(sK));
                uint32_t dV = (uint32_t)__cvta_generic_to_shared(&pool[VS_OFF(cur ^ 1) + r * 40 + jc]);
                const uint32_t* sV = &vpb[(size_t)((ci + 1) * 64 + r) * 32 + jc];
                asm volatile("cp.async.cg.shared.global [%0], [%1], 16;" :: "r"(dV), "l"(sV));
            }
            asm volatile("cp.async.commit_group;" ::: "memory");
            asm volatile("cp.async.wait_group 1;" ::: "memory");
        } else {
            asm volatile("cp.async.wait_group 0;" ::: "memory");
        }
        __syncthreads();

        const uint32_t* Kc = &pool[KS_OFF(cur)];
        const uint32_t* Vc = &pool[VS_OFF(cur)];
        #pragma unroll
        for (int nt = 0; nt < 8; nt++) {
            // ---- QK: full K fragment row in 2 LDS.128 ----
            uint4 kw0 = *(const uint4*)&Kc[(nt * 8 + gid) * 36 + tig * 8];
            uint4 kw1 = *(const uint4*)&Kc[(nt * 8 + gid) * 36 + tig * 8 + 4];
            float S[4] = {0.f, 0.f, 0.f, 0.f};
            mma_tf32(S, qA[0], kw0.x, kw0.y);
            mma_tf32(S, qA[1], kw0.z, kw0.w);
            mma_tf32(S, qA[2], kw1.x, kw1.y);
            mma_tf32(S, qA[3], kw1.z, kw1.w);
            // ---- exp + row-sum partials ----
            float p0 = __expf(S[0] * SCL);
            float p1 = __expf(S[1] * SCL);
            float p2 = __expf(S[2] * SCL);
            float p3 = __expf(S[3] * SCL);
            l_lo += p0 + p1;
            l_hi += p2 + p3;
            // ---- C-frag -> A-frag exchange via quad shuffles ----
            int s1 = (lane & ~3) | (tig >> 1);
            int s2 = s1 + 2;
            float a0q = __shfl_sync(0xFFFFFFFFu, p0, s1);
            float a1q = __shfl_sync(0xFFFFFFFFu, p1, s1);
            float a2q = __shfl_sync(0xFFFFFFFFu, p2, s1);
            float a3q = __shfl_sync(0xFFFFFFFFu, p3, s1);
            float a0r = __shfl_sync(0xFFFFFFFFu, p0, s2);
            float a1r = __shfl_sync(0xFFFFFFFFu, p1, s2);
            float a2r = __shfl_sync(0xFFFFFFFFu, p2, s2);
            float a3r = __shfl_sync(0xFFFFFFFFu, p3, s2);
            bool e = (tig & 1);
            uint32_t pA[4];
            pA[0] = f2tf(e ? a1q : a0q);
            pA[1] = f2tf(e ? a3q : a2q);
            pA[2] = f2tf(e ? a1r : a0r);
            pA[3] = f2tf(e ? a3r : a2r);
            // ---- AV: V fragment rows in 2 LDS.128 ----
            uint4 vw0 = *(const uint4*)&Vc[(nt * 8 + tig) * 40 + gid * 4];
            uint4 vw1 = *(const uint4*)&Vc[(nt * 8 + tig + 4) * 40 + gid * 4];
            mma_tf32(O[0], pA, vw0.x, vw1.x);
            mma_tf32(O[1], pA, vw0.y, vw1.y);
            mma_tf32(O[2], pA, vw0.z, vw1.z);
            mma_tf32(O[3], pA, vw0.w, vw1.w);
        }
        __syncthreads();
    }

    // ---- reduce l across the tig quad, normalize, write ----
    l_lo += __shfl_xor_sync(0xFFFFFFFF, l_lo, 1);
    l_lo += __shfl_xor_sync(0xFFFFFFFF, l_lo, 2);
    l_hi += __shfl_xor_sync(0xFFFFFFFF, l_hi, 1);
    l_hi += __shfl_xor_sync(0xFFFFFFFF, l_hi, 2);
    float inv_lo = 1.0f / l_lo;
    float inv_hi = 1.0f / l_hi;

    const int rlo = n0 + warp * 16 + gid;
    const int rhi = rlo + 8;
    #pragma unroll
    for (int mt = 0; mt < 4; mt++) {
        int c = h * 32 + mt * 8 + 2 * tig;
        float2 lo = make_float2(O[mt][0] * inv_lo, O[mt][1] * inv_lo);
        float2 hi = make_float2(O[mt][2] * inv_hi, O[mt][3] * inv_hi);
        *(float2*)&pre[((size_t)b * 4096 + rlo) * 256 + c] = lo;
        *(float2*)&pre[((size_t)b * 4096 + rhi) * 256 + c] = hi;
    }
}

// =================================================================================
// depthwise 7x7 conv (pad 3), reads planar v copy (coalesced) -> g_vpe[b][m][c]
// =================================================================================
__global__ __launch_bounds__(256) void k_dwconv(
    const float* __restrict__ vt, const float* __restrict__ Wpe,
    const float* __restrict__ pe_scale, const float* __restrict__ pe_bias,
    float* __restrict__ vpe)
{
    __shared__ float plane[1024];
    __shared__ float wsm[49];
    const int c = blockIdx.x;
    const int b = blockIdx.y;
    const int tid = threadIdx.x;

    *(float4*)&plane[tid * 4] = *(const float4*)&vt[((size_t)b * 256 + c) * 1024 + tid * 4];
    if (tid < 49) wsm[tid] = Wpe[c * 49 + tid];
    __syncthreads();

    const float sc = pe_scale[c], bi = pe_bias[c];
    #pragma unroll
    for (int i = 0; i < 4; i++) {
        int m = tid + 256 * i;
        int y = m >> 5, x = m & 31;
        float s = 0.0f;
        #pragma unroll
        for (int ky = 0; ky < 7; ky++) {
            int iy = y + ky - 3;
            if ((unsigned)iy < 32u) {
                #pragma unroll
                for (int kx = 0; kx < 7; kx++) {
                    int ix = x + kx - 3;
                    if ((unsigned)ix < 32u) s += plane[iy * 32 + ix] * wsm[ky * 7 + kx];
                }
            }
        }
        vpe[((size_t)b * 1024 + m) * 256 + c] = s * sc + bi;
    }
}

// =================================================================================
// bilinear x2 upsample + add into pre
// =================================================================================
__global__ __launch_bounds__(256) void k_upsample_add(
    const float* __restrict__ vpe, float* __restrict__ pre)
{
    const int y = blockIdx.x;
    const int b = blockIdx.y;
    const int c = threadIdx.x;

    float ys = y * 0.5f - 0.25f;
    int y0 = (int)floorf(ys);
    float wy = ys - (float)y0;
    int y0c = max(y0, 0), y1c = min(y0 + 1, 31);

    const float* vb = vpe + (size_t)b * 1024 * 256;

    for (int x = 0; x < 64; x++) {
        float xs = x * 0.5f - 0.25f;
        int x0 = (int)floorf(xs);
        float wx = xs - (float)x0;
        int x0c = max(x0, 0), x1c = min(x0 + 1, 31);

        float v00 = vb[(y0c * 32 + x0c) * 256 + c];
        float v01 = vb[(y0c * 32 + x1c) * 256 + c];
        float v10 = vb[(y1c * 32 + x0c) * 256 + c];
        float v11 = vb[(y1c * 32 + x1c) * 256 + c];
        float val = (1.f - wy) * ((1.f - wx) * v00 + wx * v01)
                  +        wy  * ((1.f - wx) * v10 + wx * v11);

        size_t o = ((size_t)b * 4096 + y * 64 + x) * 256 + c;
        pre[o] += val;
    }
}

// =================================================================================
// launch — kv-conv + dwconv chain overlapped on a second stream
// =================================================================================
extern "C" void kernel_launch(void* const* d_in, const int* in_sizes, int n_in,
                              void* d_out, int out_size)
{
    (void)in_sizes; (void)n_in; (void)out_size;
    const float* x          = (const float*)d_in[0];
    const float* upper_feat = (const float*)d_in[1];
    const float* Wq         = (const float*)d_in[2];
    const float* q_scale    = (const float*)d_in[3];
    const float* q_bias     = (const float*)d_in[4];
    const float* Wkv        = (const float*)d_in[5];
    const float* kv_scale   = (const float*)d_in[6];
    const float* kv_bias    = (const float*)d_in[7];
    const float* Wpe        = (const float*)d_in[8];
    const float* pe_scale   = (const float*)d_in[9];
    const float* pe_bias    = (const float*)d_in[10];
    const float* Wproj      = (const float*)d_in[11];
    const float* proj_scale = (const float*)d_in[12];
    const float* proj_bias  = (const float*)d_in[13];
    float* out = (float*)d_out;

    float *pq, *pvt, *pvpe, *ppre;
    uint32_t *pkp, *pvp;
    cudaGetSymbolAddress((void**)&pq,   g_q);
    cudaGetSymbolAddress((void**)&pkp,  g_kp);
    cudaGetSymbolAddress((void**)&pvp,  g_vp);
    cudaGetSymbolAddress((void**)&pvt,  g_vt);
    cudaGetSymbolAddress((void**)&pvpe, g_vpe);
    cudaGetSymbolAddress((void**)&ppre, g_pre);

    static cudaStream_t s2 = nullptr;
    static cudaEvent_t e_fork = nullptr, e_kv = nullptr, e_dw = nullptr;
    if (s2 == nullptr) {
        cudaStreamCreateWithFlags(&s2, cudaStreamNonBlocking);
        cudaEventCreateWithFlags(&e_fork, cudaEventDisableTiming);
        cudaEventCreateWithFlags(&e_kv,   cudaEventDisableTiming);
        cudaEventCreateWithFlags(&e_dw,   cudaEventDisableTiming);
    }

    // fork
    cudaEventRecord(e_fork, 0);
    cudaStreamWaitEvent(s2, e_fork, 0);

    // stream 2: kv conv -> dwconv
    k_conv_tf32_nmajor<<<dim3(8, 8, 4), 256, 0, s2>>>(
        upper_feat, Wkv, kv_scale, kv_bias, nullptr, pkp, pvp, pvt, 256, 1024, 512);
    cudaEventRecord(e_kv, s2);
    k_dwconv<<<dim3(256, 4), 256, 0, s2>>>(pvt, Wpe, pe_scale, pe_bias, pvpe);
    cudaEventRecord(e_dw, s2);

    // main stream: q conv, then attention (needs kv)
    k_conv_tf32_nmajor<<<dim3(4, 32, 4), 256>>>(
        x, Wq, q_scale, q_bias, pq, nullptr, nullptr, nullptr, 256, 4096, 256);
    cudaStreamWaitEvent(0, e_kv, 0);
    k_attn_mma3<<<dim3(32, 32), 256>>>(
        (const uint32_t*)pq, pkp, pvp, ppre);

    // join: upsample needs attention (stream order) + dwconv (event)
    cudaStreamWaitEvent(0, e_dw, 0);
    k_upsample_add<<<dim3(64, 4), 256>>>(pvpe, ppre);
    k_conv_tf32_proj<<<dim3(2, 64, 4), 256>>>(ppre, Wproj, proj_scale, proj_bias, out, 256, 4096, 256);
}

// round 11
// speedup vs baseline: 1.4669x; 1.4669x over previous
#include <cuda_runtime.h>
#include <cuda_fp16.h>
#include <math.h>
#include <stdint.h>

// ---------------- scratch (static device globals; no allocation) ----------------
__device__ uint32_t g_qh [(size_t)4 * 4096 * 128];     // [b][n][128 half2]  q fp16
__device__ uint32_t g_kp [(size_t)4 * 8 * 1024 * 16];  // [b][h][m][16 half2] K frag-perm
__device__ uint32_t g_vp [(size_t)4 * 8 * 16 * 1024];  // [b][h][ci][d][32 half2] V frag-perm
__device__ float    g_vt [(size_t)4 * 256 * 1024];     // [b][c][m] fp32 planar v
__device__ float    g_vpe[(size_t)4 * 1024 * 256];     // [b][m][c]
__device__ float    g_pre[(size_t)4 * 4096 * 256];     // [b][n][c]

// ---------------- helpers ----------------
__device__ __forceinline__ uint32_t f2tf(float f) {
    uint32_t r; asm("cvt.rna.tf32.f32 %0, %1;" : "=r"(r) : "f"(f)); return r;
}
__device__ __forceinline__ void mma_tf32(float c[4], const uint32_t a[4],
                                         uint32_t b0, uint32_t b1) {
    asm("mma.sync.aligned.m16n8k8.row.col.f32.tf32.tf32.f32 "
        "{%0,%1,%2,%3}, {%4,%5,%6,%7}, {%8,%9}, {%0,%1,%2,%3};"
        : "+f"(c[0]), "+f"(c[1]), "+f"(c[2]), "+f"(c[3])
        : "r"(a[0]), "r"(a[1]), "r"(a[2]), "r"(a[3]), "r"(b0), "r"(b1));
}
__device__ __forceinline__ void mma_fp16(float c[4], const uint32_t a[4],
                                         uint32_t b0, uint32_t b1) {
    asm("mma.sync.aligned.m16n8k16.row.col.f32.f16.f16.f32 "
        "{%0,%1,%2,%3}, {%4,%5,%6,%7}, {%8,%9}, {%0,%1,%2,%3};"
        : "+f"(c[0]), "+f"(c[1]), "+f"(c[2]), "+f"(c[3])
        : "r"(a[0]), "r"(a[1]), "r"(a[2]), "r"(a[3]), "r"(b0), "r"(b1));
}
__device__ __forceinline__ uint32_t packh2(float a, float b) {
    __half2 h = __floats2half2_rn(a, b);
    return *(uint32_t*)&h;
}

// =================================================================================
// tf32 conv1x1, input planar [C][Nsp], pipelined loads.
// q mode (qh!=null): fp16 half2 output [n][O/2 words].
// kv mode (kp!=null): K/V fragment-permuted fp16 buffers + fp32 planar v.
// =================================================================================
__global__ __launch_bounds__(256) void k_conv_tf32_nmajor(
    const float* __restrict__ X, const float* __restrict__ W,
    const float* __restrict__ scale, const float* __restrict__ bias,
    uint32_t* __restrict__ qh, uint32_t* __restrict__ kp, uint32_t* __restrict__ vp,
    float* __restrict__ vt, int C, int Nsp, int O)
{
    __shared__ __align__(16) uint32_t As[32 * 136];
    __shared__ __align__(16) uint32_t Ws[64 * 36];
    const int b  = blockIdx.z;
    const int n0 = blockIdx.y * 128;
    const int o0 = blockIdx.x * 64;
    const int tid = threadIdx.x;
    const int warp = tid >> 5, lane = tid & 31;
    const int gid = lane >> 2, tig = lane & 3;
    const int wm = warp * 16;

    const float* Xb = X + (size_t)b * C * Nsp;
    float Cacc[8][4];
    #pragma unroll
    for (int i = 0; i < 8; i++)
        #pragma unroll
        for (int j = 0; j < 4; j++) Cacc[i][j] = 0.0f;

    float4 ra[4], rb[2];
    #pragma unroll
    for (int i = 0; i < 4; i++) {
        int idx = tid + 256 * i;
        int k = idx >> 5, mq = (idx & 31) * 4;
        ra[i] = *(const float4*)&Xb[(size_t)k * Nsp + n0 + mq];
    }
    #pragma unroll
    for (int i = 0; i < 2; i++) {
        int idx = tid + 256 * i;
        int o = idx >> 3, kq = (idx & 7) * 4;
        rb[i] = *(const float4*)&W[(size_t)(o0 + o) * C + kq];
    }

    for (int c0 = 0; c0 < C; c0 += 32) {
        #pragma unroll
        for (int i = 0; i < 4; i++) {
            int idx = tid + 256 * i;
            int k = idx >> 5, mq = (idx & 31) * 4;
            uint4 u; u.x = f2tf(ra[i].x); u.y = f2tf(ra[i].y);
                     u.z = f2tf(ra[i].z); u.w = f2tf(ra[i].w);
            *(uint4*)&As[k * 136 + mq] = u;
        }
        #pragma unroll
        for (int i = 0; i < 2; i++) {
            int idx = tid + 256 * i;
            int o = idx >> 3, kq = (idx & 7) * 4;
            uint4 u; u.x = f2tf(rb[i].x); u.y = f2tf(rb[i].y);
                     u.z = f2tf(rb[i].z); u.w = f2tf(rb[i].w);
            *(uint4*)&Ws[o * 36 + kq] = u;
        }
        __syncthreads();
        if (c0 + 32 < C) {
            #pragma unroll
            for (int i = 0; i < 4; i++) {
                int idx = tid + 256 * i;
                int k = idx >> 5, mq = (idx & 31) * 4;
                ra[i] = *(const float4*)&Xb[(size_t)(c0 + 32 + k) * Nsp + n0 + mq];
            }
            #pragma unroll
            for (int i = 0; i < 2; i++) {
                int idx = tid + 256 * i;
                int o = idx >> 3, kq = (idx & 7) * 4;
                rb[i] = *(const float4*)&W[(size_t)(o0 + o) * C + c0 + 32 + kq];
            }
        }
        #pragma unroll
        for (int ks = 0; ks < 4; ks++) {
            int kk = ks * 8 + tig;
            uint32_t aF[4];
            aF[0] = As[kk * 136 + wm + gid];
            aF[1] = As[kk * 136 + wm + gid + 8];
            aF[2] = As[(kk + 4) * 136 + wm + gid];
            aF[3] = As[(kk + 4) * 136 + wm + gid + 8];
            #pragma unroll
            for (int nt = 0; nt < 8; nt++) {
                uint32_t b0 = Ws[(nt * 8 + gid) * 36 + kk];
                uint32_t b1 = Ws[(nt * 8 + gid) * 36 + kk + 4];
                mma_tf32(Cacc[nt], aF, b0, b1);
            }
        }
        __syncthreads();
    }

    const int nlo = n0 + wm + gid, nhi = nlo + 8;
    #pragma unroll
    for (int nt = 0; nt < 8; nt++) {
        int o = o0 + nt * 8 + 2 * tig;          // even channel
        float2 sc = *(const float2*)&scale[o];
        float2 bi = *(const float2*)&bias[o];
        float2 lo, hi;
        lo.x = Cacc[nt][0] * sc.x + bi.x;
        lo.y = Cacc[nt][1] * sc.y + bi.y;
        hi.x = Cacc[nt][2] * sc.x + bi.x;
        hi.y = Cacc[nt][3] * sc.y + bi.y;

        if (qh != nullptr) {
            // q mode: fp16 half2 words [b][n][O/2]
            qh[((size_t)b * Nsp + nlo) * (O >> 1) + (o >> 1)] = packh2(lo.x, lo.y);
            qh[((size_t)b * Nsp + nhi) * (O >> 1) + (o >> 1)] = packh2(hi.x, hi.y);
        } else {
            int h = o >> 6;
            int c = o & 63;
            if (c < 32) {
                // K: word w holds channels (c, c+1); w = ((c&7)>>1)*4 + j
                int w = ((c & 7) >> 1) * 4 + (((c >> 3) & 1) | (((c >> 4) & 1) << 1));
                size_t base = ((size_t)b * 8 + h) * 1024;
                kp[(base + nlo) * 16 + w] = packh2(lo.x, lo.y);
                kp[(base + nhi) * 16 + w] = packh2(hi.x, hi.y);
            } else {
                // V: half scatter into [b][h][ci][d][pos] words, pairing rows (2pr,2pr+1)
                int cv = c - 32;
                __half* vph = (__half*)vp;
                size_t bhb = ((size_t)b * 8 + h) * 16 * 1024 * 2;   // halfs
                #pragma unroll
                for (int sel = 0; sel < 4; sel++) {
                    int m = (sel & 2) ? nhi : nlo;
                    int d = cv + (sel & 1);
                    float v = (sel == 0) ? lo.x : (sel == 1) ? lo.y : (sel == 2) ? hi.x : hi.y;
                    int ci = m >> 6, rm = m & 63;
                    int pr = rm >> 1, lb = rm & 1;
                    int pos = (pr & 3) * 8 + (pr >> 2);
                    vph[bhb + (((size_t)ci * 32 + d) * 32 + pos) * 2 + lb] = __float2half_rn(v);
                }
                // fp32 planar v for dwconv
                int vc = h * 32 + cv;
                vt[((size_t)b * 256 + vc)     * Nsp + nlo] = lo.x;
                vt[((size_t)b * 256 + vc + 1) * Nsp + nlo] = lo.y;
                vt[((size_t)b * 256 + vc)     * Nsp + nhi] = hi.x;
                vt[((size_t)b * 256 + vc + 1) * Nsp + nhi] = hi.y;
            }
        }
    }
}

// =================================================================================
// tf32 conv1x1 projection: input row-major [Nsp][C], output planar [O][Nsp]
// =================================================================================
__global__ __launch_bounds__(256) void k_conv_tf32_proj(
    const float* __restrict__ Ain, const float* __restrict__ W,
    const float* __restrict__ scale, const float* __restrict__ bias,
    float* __restrict__ out, int C, int Nsp, int O)
{
    __shared__ __align__(16) uint32_t Wa[128 * 36];
    __shared__ __align__(16) uint32_t Ab[64 * 36];
    const int b  = blockIdx.z;
    const int o0 = blockIdx.x * 128;
    const int n0 = blockIdx.y * 64;
    const int tid = threadIdx.x;
    const int warp = tid >> 5, lane = tid & 31;
    const int gid = lane >> 2, tig = lane & 3;
    const int wm = warp * 16;

    const float* Ainb = Ain + (size_t)b * Nsp * C;
    float Cacc[8][4];
    #pragma unroll
    for (int i = 0; i < 8; i++)
        #pragma unroll
        for (int j = 0; j < 4; j++) Cacc[i][j] = 0.0f;

    float4 ra[4], rb[2];
    #pragma unroll
    for (int i = 0; i < 4; i++) {
        int idx = tid + 256 * i;
        int o = idx >> 3, kq = (idx & 7) * 4;
        ra[i] = *(const float4*)&W[(size_t)(o0 + o) * C + kq];
    }
    #pragma unroll
    for (int i = 0; i < 2; i++) {
        int idx = tid + 256 * i;
        int n = idx >> 3, kq = (idx & 7) * 4;
        rb[i] = *(const float4*)&Ainb[(size_t)(n0 + n) * C + kq];
    }

    for (int c0 = 0; c0 < C; c0 += 32) {
        #pragma unroll
        for (int i = 0; i < 4; i++) {
            int idx = tid + 256 * i;
            int o = idx >> 3, kq = (idx & 7) * 4;
            uint4 u; u.x = f2tf(ra[i].x); u.y = f2tf(ra[i].y);
                     u.z = f2tf(ra[i].z); u.w = f2tf(ra[i].w);
            *(uint4*)&Wa[o * 36 + kq] = u;
        }
        #pragma unroll
        for (int i = 0; i < 2; i++) {
            int idx = tid + 256 * i;
            int n = idx >> 3, kq = (idx & 7) * 4;
            uint4 u; u.x = f2tf(rb[i].x); u.y = f2tf(rb[i].y);
                     u.z = f2tf(rb[i].z); u.w = f2tf(rb[i].w);
            *(uint4*)&Ab[n * 36 + kq] = u;
        }
        __syncthreads();
        if (c0 + 32 < C) {
            #pragma unroll
            for (int i = 0; i < 4; i++) {
                int idx = tid + 256 * i;
                int o = idx >> 3, kq = (idx & 7) * 4;
                ra[i] = *(const float4*)&W[(size_t)(o0 + o) * C + c0 + 32 + kq];
            }
            #pragma unroll
            for (int i = 0; i < 2; i++) {
                int idx = tid + 256 * i;
                int n = idx >> 3, kq = (idx & 7) * 4;
                rb[i] = *(const float4*)&Ainb[(size_t)(n0 + n) * C + c0 + 32 + kq];
            }
        }
        #pragma unroll
        for (int ks = 0; ks < 4; ks++) {
            int kk = ks * 8 + tig;
            uint32_t aF[4];
            aF[0] = Wa[(wm + gid) * 36 + kk];
            aF[1] = Wa[(wm + gid + 8) * 36 + kk];
            aF[2] = Wa[(wm + gid) * 36 + kk + 4];
            aF[3] = Wa[(wm + gid + 8) * 36 + kk + 4];
            #pragma unroll
            for (int nt = 0; nt < 8; nt++) {
                uint32_t b0 = Ab[(nt * 8 + gid) * 36 + kk];
                uint32_t b1 = Ab[(nt * 8 + gid) * 36 + kk + 4];
                mma_tf32(Cacc[nt], aF, b0, b1);
            }
        }
        __syncthreads();
    }

    const int olo = o0 + wm + gid, ohi = olo + 8;
    const float sclo = scale[olo], bilo = bias[olo];
    const float schi = scale[ohi], bihi = bias[ohi];
    #pragma unroll
    for (int nt = 0; nt < 8; nt++) {
        int n = n0 + nt * 8 + 2 * tig;
        float2 lo, hi;
        lo.x = Cacc[nt][0] * sclo + bilo;
        lo.y = Cacc[nt][1] * sclo + bilo;
        hi.x = Cacc[nt][2] * schi + bihi;
        hi.y = Cacc[nt][3] * schi + bihi;
        *(float2*)&out[((size_t)b * O + olo) * Nsp + n] = lo;
        *(float2*)&out[((size_t)b * O + ohi) * Nsp + n] = hi;
    }
}

// =================================================================================
// attention v5: fp16 m16n8k16. Zero-shuffle P pipeline (C-frag == A-frag cols).
// K/V fragment-permuted fp16, cp.async double buffer.
// pool: [K0|K1 : 2x64x16] [V0|V1 : 2x32x36] words (17.4 KB).
// =================================================================================
#define KO(bf) ((bf) * 1024)
#define VO(bf) (2048 + (bf) * 1152)

__global__ __launch_bounds__(256) void k_attn_fp16(
    const uint32_t* __restrict__ qh, const uint32_t* __restrict__ kp,
    const uint32_t* __restrict__ vp, float* __restrict__ pre)
{
    __shared__ __align__(16) uint32_t pool[4352];

    const int bh = blockIdx.y;
    const int b = bh >> 3, h = bh & 7;
    const int tid = threadIdx.x;
    const int warp = tid >> 5, lane = tid & 31;
    const int gid = lane >> 2, tig = lane & 3;
    const int n0 = blockIdx.x * 128;

    // ---- stage q tile [128][16 words] (stride 17), build fp16 A-frags ----
    {
        const uint32_t* qb = qh + ((size_t)b * 4096 + n0) * 128 + h * 16;
        #pragma unroll
        for (int i = 0; i < 2; i++) {
            int idx = tid + 256 * i;          // 0..511
            int r = idx >> 2, seg = (idx & 3) * 4;
            uint4 t = *(const uint4*)&qb[(size_t)r * 128 + seg];
            pool[r * 17 + seg + 0] = t.x;
            pool[r * 17 + seg + 1] = t.y;
            pool[r * 17 + seg + 2] = t.z;
            pool[r * 17 + seg + 3] = t.w;
        }
    }
    __syncthreads();

    uint32_t qA[2][4];
    {
        int r0 = warp * 16 + gid;
        #pragma unroll
        for (int ks = 0; ks < 2; ks++) {
            int w = 8 * ks + tig;
            qA[ks][0] = pool[r0 * 17 + w];
            qA[ks][1] = pool[(r0 + 8) * 17 + w];
            qA[ks][2] = pool[r0 * 17 + w + 4];
            qA[ks][3] = pool[(r0 + 8) * 17 + w + 4];
        }
    }
    __syncthreads();

    const uint32_t* kpb = kp + ((size_t)b * 8 + h) * 1024 * 16;
    const uint32_t* vpb = vp + ((size_t)b * 8 + h) * 16 * 1024;

    // prefetch chunk 0 (one 16B cp.async each for K and V per thread)
    {
        int rk = tid >> 2, sk = (tid & 3) * 4;
        uint32_t dK = (uint32_t)__cvta_generic_to_shared(&pool[KO(0) + rk * 16 + sk]);
        asm volatile("cp.async.cg.shared.global [%0], [%1], 16;"
                     :: "r"(dK), "l"(&kpb[(size_t)rk * 16 + sk]));
        int dv = tid >> 3, sv = (tid & 7) * 4;
        uint32_t dV = (uint32_t)__cvta_generic_to_shared(&pool[VO(0) + dv * 36 + sv]);
        asm volatile("cp.async.cg.shared.global [%0], [%1], 16;"
                     :: "r"(dV), "l"(&vpb[(size_t)dv * 32 + sv]));
    }
    asm volatile("cp.async.commit_group;" ::: "memory");

    float O[4][4];
    #pragma unroll
    for (int i = 0; i < 4; i++)
        #pragma unroll
        for (int j = 0; j < 4; j++) O[i][j] = 0.0f;
    float l_lo = 0.0f, l_hi = 0.0f;
    const float SCL = 0.17677669529663687f;   // 1/sqrt(32)

    for (int ci = 0; ci < 16; ci++) {
        const int cur = ci & 1;
        if (ci < 15) {
            int rk = tid >> 2, sk = (tid & 3) * 4;
            uint32_t dK = (uint32_t)__cvta_generic_to_shared(&pool[KO(cur ^ 1) + rk * 16 + sk]);
            asm volatile("cp.async.cg.shared.global [%0], [%1], 16;"
                         :: "r"(dK), "l"(&kpb[(size_t)((ci + 1) * 64 + rk) * 16 + sk]));
            int dv = tid >> 3, sv = (tid & 7) * 4;
            uint32_t dV = (uint32_t)__cvta_generic_to_shared(&pool[VO(cur ^ 1) + dv * 36 + sv]);
            asm volatile("cp.async.cg.shared.global [%0], [%1], 16;"
                         :: "r"(dV), "l"(&vpb[(size_t)(ci + 1) * 1024 + dv * 32 + sv]));
            asm volatile("cp.async.commit_group;" ::: "memory");
            asm volatile("cp.async.wait_group 1;" ::: "memory");
        } else {
            asm volatile("cp.async.wait_group 0;" ::: "memory");
        }
        __syncthreads();

        const uint32_t* Kc = &pool[KO(cur)];
        const uint32_t* Vc = &pool[VO(cur)];
        uint4 vr[4];
        #pragma unroll
        for (int g = 0; g < 4; g++) {
            // ---- QK for kv cols [16g, 16g+16): two n8 tiles ----
            uint4 kwA = *(const uint4*)&Kc[((2 * g) * 8 + gid) * 16 + tig * 4];
            uint4 kwB = *(const uint4*)&Kc[((2 * g + 1) * 8 + gid) * 16 + tig * 4];
            float S0[4] = {0.f, 0.f, 0.f, 0.f};
            float S1[4] = {0.f, 0.f, 0.f, 0.f};
            mma_fp16(S0, qA[0], kwA.x, kwA.y);
            mma_fp16(S0, qA[1], kwA.z, kwA.w);
            mma_fp16(S1, qA[0], kwB.x, kwB.y);
            mma_fp16(S1, qA[1], kwB.z, kwB.w);
            // ---- exp + row-sum partials ----
            float p00 = __expf(S0[0] * SCL), p01 = __expf(S0[1] * SCL);
            float p02 = __expf(S0[2] * SCL), p03 = __expf(S0[3] * SCL);
            float p10 = __expf(S1[0] * SCL), p11 = __expf(S1[1] * SCL);
            float p12 = __expf(S1[2] * SCL), p13 = __expf(S1[3] * SCL);
            l_lo += (p00 + p01) + (p10 + p11);
            l_hi += (p02 + p03) + (p12 + p13);
            // ---- C-frag IS the A-frag: direct pack, no shuffles ----
            uint32_t pA[4];
            pA[0] = packh2(p00, p01);
            pA[1] = packh2(p02, p03);
            pA[2] = packh2(p10, p11);
            pA[3] = packh2(p12, p13);
            // ---- AV k16 step g ----
            if ((g & 1) == 0) {
                #pragma unroll
                for (int mt = 0; mt < 4; mt++)
                    vr[mt] = *(const uint4*)&Vc[(mt * 8 + gid) * 36 + tig * 8 + 2 * g];
            }
            if ((g & 1) == 0) {
                #pragma unroll
                for (int mt = 0; mt < 4; mt++)
                    mma_fp16(O[mt], pA, vr[mt].x, vr[mt].y);
            } else {
                #pragma unroll
                for (int mt = 0; mt < 4; mt++)
                    mma_fp16(O[mt], pA, vr[mt].z, vr[mt].w);
            }
        }
        __syncthreads();
    }

    // ---- reduce l across the tig quad, normalize, write ----
    l_lo += __shfl_xor_sync(0xFFFFFFFF, l_lo, 1);
    l_lo += __shfl_xor_sync(0xFFFFFFFF, l_lo, 2);
    l_hi += __shfl_xor_sync(0xFFFFFFFF, l_hi, 1);
    l_hi += __shfl_xor_sync(0xFFFFFFFF, l_hi, 2);
    float inv_lo = 1.0f / l_lo;
    float inv_hi = 1.0f / l_hi;

    const int rlo = n0 + warp * 16 + gid;
    const int rhi = rlo + 8;
    #pragma unroll
    for (int mt = 0; mt < 4; mt++) {
        int c = h * 32 + mt * 8 + 2 * tig;
        float2 lo = make_float2(O[mt][0] * inv_lo, O[mt][1] * inv_lo);
        float2 hi = make_float2(O[mt][2] * inv_hi, O[mt][3] * inv_hi);
        *(float2*)&pre[((size_t)b * 4096 + rlo) * 256 + c] = lo;
        *(float2*)&pre[((size_t)b * 4096 + rhi) * 256 + c] = hi;
    }
}

// =================================================================================
// depthwise 7x7 conv (pad 3), planar v input -> g_vpe[b][m][c]
// =================================================================================
__global__ __launch_bounds__(256) void k_dwconv(
    const float* __restrict__ vt, const float* __restrict__ Wpe,
    const float* __restrict__ pe_scale, const float* __restrict__ pe_bias,
    float* __restrict__ vpe)
{
    __shared__ float plane[1024];
    __shared__ float wsm[49];
    const int c = blockIdx.x;
    const int b = blockIdx.y;
    const int tid = threadIdx.x;

    *(float4*)&plane[tid * 4] = *(const float4*)&vt[((size_t)b * 256 + c) * 1024 + tid * 4];
    if (tid < 49) wsm[tid] = Wpe[c * 49 + tid];
    __syncthreads();

    const float sc = pe_scale[c], bi = pe_bias[c];
    #pragma unroll
    for (int i = 0; i < 4; i++) {
        int m = tid + 256 * i;
        int y = m >> 5, x = m & 31;
        float s = 0.0f;
        #pragma unroll
        for (int ky = 0; ky < 7; ky++) {
            int iy = y + ky - 3;
            if ((unsigned)iy < 32u) {
                #pragma unroll
                for (int kx = 0; kx < 7; kx++) {
                    int ix = x + kx - 3;
                    if ((unsigned)ix < 32u) s += plane[iy * 32 + ix] * wsm[ky * 7 + kx];
                }
            }
        }
        vpe[((size_t)b * 1024 + m) * 256 + c] = s * sc + bi;
    }
}

// =================================================================================
// bilinear x2 upsample + add into pre
// =================================================================================
__global__ __launch_bounds__(256) void k_upsample_add(
    const float* __restrict__ vpe, float* __restrict__ pre)
{
    const int y = blockIdx.x;
    const int b = blockIdx.y;
    const int c = threadIdx.x;

    float ys = y * 0.5f - 0.25f;
    int y0 = (int)floorf(ys);
    float wy = ys - (float)y0;
    int y0c = max(y0, 0), y1c = min(y0 + 1, 31);

    const float* vb = vpe + (size_t)b * 1024 * 256;

    for (int x = 0; x < 64; x++) {
        float xs = x * 0.5f - 0.25f;
        int x0 = (int)floorf(xs);
        float wx = xs - (float)x0;
        int x0c = max(x0, 0), x1c = min(x0 + 1, 31);

        float v00 = vb[(y0c * 32 + x0c) * 256 + c];
        float v01 = vb[(y0c * 32 + x1c) * 256 + c];
        float v10 = vb[(y1c * 32 + x0c) * 256 + c];
        float v11 = vb[(y1c * 32 + x1c) * 256 + c];
        float val = (1.f - wy) * ((1.f - wx) * v00 + wx * v01)
                  +        wy  * ((1.f - wx) * v10 + wx * v11);

        size_t o = ((size_t)b * 4096 + y * 64 + x) * 256 + c;
        pre[o] += val;
    }
}

// =================================================================================
// launch — kv-conv + dwconv chain overlapped on a second stream
// =================================================================================
extern "C" void kernel_launch(void* const* d_in, const int* in_sizes, int n_in,
                              void* d_out, int out_size)
{
    (void)in_sizes; (void)n_in; (void)out_size;
    const float* x          = (const float*)d_in[0];
    const float* upper_feat = (const float*)d_in[1];
    const float* Wq         = (const float*)d_in[2];
    const float* q_scale    = (const float*)d_in[3];
    const float* q_bias     = (const float*)d_in[4];
    const float* Wkv        = (const float*)d_in[5];
    const float* kv_scale   = (const float*)d_in[6];
    const float* kv_bias    = (const float*)d_in[7];
    const float* Wpe        = (const float*)d_in[8];
    const float* pe_scale   = (const float*)d_in[9];
    const float* pe_bias    = (const float*)d_in[10];
    const float* Wproj      = (const float*)d_in[11];
    const float* proj_scale = (const float*)d_in[12];
    const float* proj_bias  = (const float*)d_in[13];
    float* out = (float*)d_out;

    float *pvt, *pvpe, *ppre;
    uint32_t *pqh, *pkp, *pvp;
    cudaGetSymbolAddress((void**)&pqh,  g_qh);
    cudaGetSymbolAddress((void**)&pkp,  g_kp);
    cudaGetSymbolAddress((void**)&pvp,  g_vp);
    cudaGetSymbolAddress((void**)&pvt,  g_vt);
    cudaGetSymbolAddress((void**)&pvpe, g_vpe);
    cudaGetSymbolAddress((void**)&ppre, g_pre);

    static cudaStream_t s2 = nullptr;
    static cudaEvent_t e_fork = nullptr, e_kv = nullptr, e_dw = nullptr;
    if (s2 == nullptr) {
        cudaStreamCreateWithFlags(&s2, cudaStreamNonBlocking);
        cudaEventCreateWithFlags(&e_fork, cudaEventDisableTiming);
        cudaEventCreateWithFlags(&e_kv,   cudaEventDisableTiming);
        cudaEventCreateWithFlags(&e_dw,   cudaEventDisableTiming);
    }

    // fork
    cudaEventRecord(e_fork, 0);
    cudaStreamWaitEvent(s2, e_fork, 0);

    // stream 2: kv conv -> dwconv
    k_conv_tf32_nmajor<<<dim3(8, 8, 4), 256, 0, s2>>>(
        upper_feat, Wkv, kv_scale, kv_bias, nullptr, pkp, pvp, pvt, 256, 1024, 512);
    cudaEventRecord(e_kv, s2);
    k_dwconv<<<dim3(256, 4), 256, 0, s2>>>(pvt, Wpe, pe_scale, pe_bias, pvpe);
    cudaEventRecord(e_dw, s2);

    // main stream: q conv, then attention (needs kv)
    k_conv_tf32_nmajor<<<dim3(4, 32, 4), 256>>>(
        x, Wq, q_scale, q_bias, pqh, nullptr, nullptr, nullptr, 256, 4096, 256);
    cudaStreamWaitEvent(0, e_kv, 0);
    k_attn_fp16<<<dim3(32, 32), 256>>>(pqh, pkp, pvp, ppre);

    // join: upsample needs attention (stream order) + dwconv (event)
    cudaStreamWaitEvent(0, e_dw, 0);
    k_upsample_add<<<dim3(64, 4), 256>>>(pvpe, ppre);
    k_conv_tf32_proj<<<dim3(2, 64, 4), 256>>>(ppre, Wproj, proj_scale, proj_bias, out, 256, 4096, 256);
}

// round 12
// speedup vs baseline: 1.7191x; 1.1720x over previous
#include <cuda_runtime.h>
#include <cuda_fp16.h>
#include <math.h>
#include <stdint.h>

// ---------------- scratch (static device globals; no allocation) ----------------
__device__ uint32_t g_qh [(size_t)4 * 4096 * 128];     // [b][n][128 half2]  q fp16 (pre-scaled)
__device__ uint32_t g_kp [(size_t)4 * 8 * 1024 * 16];  // [b][h][m][16 half2] K frag-perm
__device__ uint32_t g_vp [(size_t)4 * 8 * 16 * 1024];  // [b][h][ci][d][32 half2] V frag-perm
__device__ float    g_vt [(size_t)4 * 256 * 1024];     // [b][c][m] fp32 planar v
__device__ float    g_vpe[(size_t)4 * 1024 * 256];     // [b][m][c]
__device__ float    g_pre[(size_t)4 * 4096 * 256];     // [b][n][c]  attention output only

// ---------------- helpers ----------------
__device__ __forceinline__ uint32_t f2tf(float f) {
    uint32_t r; asm("cvt.rna.tf32.f32 %0, %1;" : "=r"(r) : "f"(f)); return r;
}
__device__ __forceinline__ void mma_tf32(float c[4], const uint32_t a[4],
                                         uint32_t b0, uint32_t b1) {
    asm("mma.sync.aligned.m16n8k8.row.col.f32.tf32.tf32.f32 "
        "{%0,%1,%2,%3}, {%4,%5,%6,%7}, {%8,%9}, {%0,%1,%2,%3};"
        : "+f"(c[0]), "+f"(c[1]), "+f"(c[2]), "+f"(c[3])
        : "r"(a[0]), "r"(a[1]), "r"(a[2]), "r"(a[3]), "r"(b0), "r"(b1));
}
__device__ __forceinline__ void mma_fp16(float c[4], const uint32_t a[4],
                                         uint32_t b0, uint32_t b1) {
    asm("mma.sync.aligned.m16n8k16.row.col.f32.f16.f16.f32 "
        "{%0,%1,%2,%3}, {%4,%5,%6,%7}, {%8,%9}, {%0,%1,%2,%3};"
        : "+f"(c[0]), "+f"(c[1]), "+f"(c[2]), "+f"(c[3])
        : "r"(a[0]), "r"(a[1]), "r"(a[2]), "r"(a[3]), "r"(b0), "r"(b1));
}
__device__ __forceinline__ uint32_t packh2(float a, float b) {
    __half2 h = __floats2half2_rn(a, b);
    return *(uint32_t*)&h;
}
__device__ __forceinline__ uint32_t h2exp2(uint32_t x) {
    uint32_t r; asm("ex2.approx.f16x2 %0, %1;" : "=r"(r) : "r"(x)); return r;
}

// q pre-scale: 1/sqrt(32) * log2(e), folded so attention uses raw ex2
#define QPRESCALE ((float)(0.17677669529663687 * 1.4426950408889634))

// =================================================================================
// tf32 conv1x1, input planar [C][Nsp], pipelined loads.
// q mode (qh!=null): fp16 half2 output, values pre-multiplied by QPRESCALE.
// kv mode (kp!=null): K/V fragment-permuted fp16 buffers + fp32 planar v.
// =================================================================================
__global__ __launch_bounds__(256) void k_conv_tf32_nmajor(
    const float* __restrict__ X, const float* __restrict__ W,
    const float* __restrict__ scale, const float* __restrict__ bias,
    uint32_t* __restrict__ qh, uint32_t* __restrict__ kp, uint32_t* __restrict__ vp,
    float* __restrict__ vt, int C, int Nsp, int O)
{
    __shared__ __align__(16) uint32_t As[32 * 136];
    __shared__ __align__(16) uint32_t Ws[64 * 36];
    const int b  = blockIdx.z;
    const int n0 = blockIdx.y * 128;
    const int o0 = blockIdx.x * 64;
    const int tid = threadIdx.x;
    const int warp = tid >> 5, lane = tid & 31;
    const int gid = lane >> 2, tig = lane & 3;
    const int wm = warp * 16;

    const float* Xb = X + (size_t)b * C * Nsp;
    float Cacc[8][4];
    #pragma unroll
    for (int i = 0; i < 8; i++)
        #pragma unroll
        for (int j = 0; j < 4; j++) Cacc[i][j] = 0.0f;

    float4 ra[4], rb[2];
    #pragma unroll
    for (int i = 0; i < 4; i++) {
        int idx = tid + 256 * i;
        int k = idx >> 5, mq = (idx & 31) * 4;
        ra[i] = *(const float4*)&Xb[(size_t)k * Nsp + n0 + mq];
    }
    #pragma unroll
    for (int i = 0; i < 2; i++) {
        int idx = tid + 256 * i;
        int o = idx >> 3, kq = (idx & 7) * 4;
        rb[i] = *(const float4*)&W[(size_t)(o0 + o) * C + kq];
    }

    for (int c0 = 0; c0 < C; c0 += 32) {
        #pragma unroll
        for (int i = 0; i < 4; i++) {
            int idx = tid + 256 * i;
            int k = idx >> 5, mq = (idx & 31) * 4;
            uint4 u; u.x = f2tf(ra[i].x); u.y = f2tf(ra[i].y);
                     u.z = f2tf(ra[i].z); u.w = f2tf(ra[i].w);
            *(uint4*)&As[k * 136 + mq] = u;
        }
        #pragma unroll
        for (int i = 0; i < 2; i++) {
            int idx = tid + 256 * i;
            int o = idx >> 3, kq = (idx & 7) * 4;
            uint4 u; u.x = f2tf(rb[i].x); u.y = f2tf(rb[i].y);
                     u.z = f2tf(rb[i].z); u.w = f2tf(rb[i].w);
            *(uint4*)&Ws[o * 36 + kq] = u;
        }
        __syncthreads();
        if (c0 + 32 < C) {
            #pragma unroll
            for (int i = 0; i < 4; i++) {
                int idx = tid + 256 * i;
                int k = idx >> 5, mq = (idx & 31) * 4;
                ra[i] = *(const float4*)&Xb[(size_t)(c0 + 32 + k) * Nsp + n0 + mq];
            }
            #pragma unroll
            for (int i = 0; i < 2; i++) {
                int idx = tid + 256 * i;
                int o = idx >> 3, kq = (idx & 7) * 4;
                rb[i] = *(const float4*)&W[(size_t)(o0 + o) * C + c0 + 32 + kq];
            }
        }
        #pragma unroll
        for (int ks = 0; ks < 4; ks++) {
            int kk = ks * 8 + tig;
            uint32_t aF[4];
            aF[0] = As[kk * 136 + wm + gid];
            aF[1] = As[kk * 136 + wm + gid + 8];
            aF[2] = As[(kk + 4) * 136 + wm + gid];
            aF[3] = As[(kk + 4) * 136 + wm + gid + 8];
            #pragma unroll
            for (int nt = 0; nt < 8; nt++) {
                uint32_t b0 = Ws[(nt * 8 + gid) * 36 + kk];
                uint32_t b1 = Ws[(nt * 8 + gid) * 36 + kk + 4];
                mma_tf32(Cacc[nt], aF, b0, b1);
            }
        }
        __syncthreads();
    }

    const int nlo = n0 + wm + gid, nhi = nlo + 8;
    #pragma unroll
    for (int nt = 0; nt < 8; nt++) {
        int o = o0 + nt * 8 + 2 * tig;          // even channel
        float2 sc = *(const float2*)&scale[o];
        float2 bi = *(const float2*)&bias[o];
        float2 lo, hi;
        lo.x = Cacc[nt][0] * sc.x + bi.x;
        lo.y = Cacc[nt][1] * sc.y + bi.y;
        hi.x = Cacc[nt][2] * sc.x + bi.x;
        hi.y = Cacc[nt][3] * sc.y + bi.y;

        if (qh != nullptr) {
            // q mode: fp16 half2 words, pre-scaled for log2-domain softmax
            qh[((size_t)b * Nsp + nlo) * (O >> 1) + (o >> 1)] =
                packh2(lo.x * QPRESCALE, lo.y * QPRESCALE);
            qh[((size_t)b * Nsp + nhi) * (O >> 1) + (o >> 1)] =
                packh2(hi.x * QPRESCALE, hi.y * QPRESCALE);
        } else {
            int h = o >> 6;
            int c = o & 63;
            if (c < 32) {
                int w = ((c & 7) >> 1) * 4 + (((c >> 3) & 1) | (((c >> 4) & 1) << 1));
                size_t base = ((size_t)b * 8 + h) * 1024;
                kp[(base + nlo) * 16 + w] = packh2(lo.x, lo.y);
                kp[(base + nhi) * 16 + w] = packh2(hi.x, hi.y);
            } else {
                int cv = c - 32;
                __half* vph = (__half*)vp;
                size_t bhb = ((size_t)b * 8 + h) * 16 * 1024 * 2;
                #pragma unroll
                for (int sel = 0; sel < 4; sel++) {
                    int m = (sel & 2) ? nhi : nlo;
                    int d = cv + (sel & 1);
                    float v = (sel == 0) ? lo.x : (sel == 1) ? lo.y : (sel == 2) ? hi.x : hi.y;
                    int ci = m >> 6, rm = m & 63;
                    int pr = rm >> 1, lb = rm & 1;
                    int pos = (pr & 3) * 8 + (pr >> 2);
                    vph[bhb + (((size_t)ci * 32 + d) * 32 + pos) * 2 + lb] = __float2half_rn(v);
                }
                int vc = h * 32 + cv;
                vt[((size_t)b * 256 + vc)     * Nsp + nlo] = lo.x;
                vt[((size_t)b * 256 + vc + 1) * Nsp + nlo] = lo.y;
                vt[((size_t)b * 256 + vc)     * Nsp + nhi] = hi.x;
                vt[((size_t)b * 256 + vc + 1) * Nsp + nhi] = hi.y;
            }
        }
    }
}

// =================================================================================
// bilerp descriptor for the fused upsample (coords depend only on spatial n)
// =================================================================================
struct Bil { int r00, r01, r10, r11; float w00, w01, w10, w11; };
__device__ __forceinline__ Bil make_bil(int n) {
    int y = n >> 6, x = n & 63;
    float ys = y * 0.5f - 0.25f;
    float xs = x * 0.5f - 0.25f;
    int y0 = (int)floorf(ys), x0 = (int)floorf(xs);
    float wy = ys - (float)y0, wx = xs - (float)x0;
    int y0c = max(y0, 0), y1c = min(y0 + 1, 31);
    int x0c = max(x0, 0), x1c = min(x0 + 1, 31);
    Bil bl;
    bl.r00 = y0c * 32 + x0c; bl.r01 = y0c * 32 + x1c;
    bl.r10 = y1c * 32 + x0c; bl.r11 = y1c * 32 + x1c;
    bl.w00 = (1.f - wy) * (1.f - wx); bl.w01 = (1.f - wy) * wx;
    bl.w10 = wy * (1.f - wx);         bl.w11 = wy * wx;
    return bl;
}
__device__ __forceinline__ float4 fused_pre_load(
    const float* __restrict__ pre_row, const float* __restrict__ vb,
    const Bil& bl, int cq)
{
    float4 t   = *(const float4*)&pre_row[cq];
    float4 v00 = *(const float4*)&vb[bl.r00 * 256 + cq];
    float4 v01 = *(const float4*)&vb[bl.r01 * 256 + cq];
    float4 v10 = *(const float4*)&vb[bl.r10 * 256 + cq];
    float4 v11 = *(const float4*)&vb[bl.r11 * 256 + cq];
    t.x += bl.w00 * v00.x + bl.w01 * v01.x + bl.w10 * v10.x + bl.w11 * v11.x;
    t.y += bl.w00 * v00.y + bl.w01 * v01.y + bl.w10 * v10.y + bl.w11 * v11.y;
    t.z += bl.w00 * v00.z + bl.w01 * v01.z + bl.w10 * v10.z + bl.w11 * v11.z;
    t.w += bl.w00 * v00.w + bl.w01 * v01.w + bl.w10 * v10.w + bl.w11 * v11.w;
    return t;
}

// =================================================================================
// tf32 conv1x1 projection with FUSED upsample+add on the B-tile input:
// B[n][c] = pre[n][c] + bilerp(vpe)[n][c]. Output planar [O][Nsp].
// =================================================================================
__global__ __launch_bounds__(256) void k_conv_tf32_proj(
    const float* __restrict__ Ain, const float* __restrict__ vpe,
    const float* __restrict__ W,
    const float* __restrict__ scale, const float* __restrict__ bias,
    float* __restrict__ out, int C, int Nsp, int O)
{
    __shared__ __align__(16) uint32_t Wa[128 * 36];
    __shared__ __align__(16) uint32_t Ab[64 * 36];
    const int b  = blockIdx.z;
    const int o0 = blockIdx.x * 128;
    const int n0 = blockIdx.y * 64;
    const int tid = threadIdx.x;
    const int warp = tid >> 5, lane = tid & 31;
    const int gid = lane >> 2, tig = lane & 3;
    const int wm = warp * 16;

    const float* Ainb = Ain + (size_t)b * Nsp * C;
    const float* vb   = vpe + (size_t)b * 1024 * 256;

    // per-thread B-row descriptors (2 rows: idx = tid, tid+256)
    const int bn0 = n0 + (tid >> 3);
    const int bn1 = n0 + ((tid + 256) >> 3);
    const Bil bl0 = make_bil(bn0);
    const Bil bl1 = make_bil(bn1);
    const float* prow0 = &Ainb[(size_t)bn0 * C];
    const float* prow1 = &Ainb[(size_t)bn1 * C];
    const int bkq = (tid & 7) * 4;

    float Cacc[8][4];
    #pragma unroll
    for (int i = 0; i < 8; i++)
        #pragma unroll
        for (int j = 0; j < 4; j++) Cacc[i][j] = 0.0f;

    float4 ra[4], rb[2];
    #pragma unroll
    for (int i = 0; i < 4; i++) {
        int idx = tid + 256 * i;
        int o = idx >> 3, kq = (idx & 7) * 4;
        ra[i] = *(const float4*)&W[(size_t)(o0 + o) * C + kq];
    }
    rb[0] = fused_pre_load(prow0, vb, bl0, bkq);
    rb[1] = fused_pre_load(prow1, vb, bl1, bkq);

    for (int c0 = 0; c0 < C; c0 += 32) {
        #pragma unroll
        for (int i = 0; i < 4; i++) {
            int idx = tid + 256 * i;
            int o = idx >> 3, kq = (idx & 7) * 4;
            uint4 u; u.x = f2tf(ra[i].x); u.y = f2tf(ra[i].y);
                     u.z = f2tf(ra[i].z); u.w = f2tf(ra[i].w);
            *(uint4*)&Wa[o * 36 + kq] = u;
        }
        #pragma unroll
        for (int i = 0; i < 2; i++) {
            int idx = tid + 256 * i;
            int n = idx >> 3, kq = (idx & 7) * 4;
            uint4 u; u.x = f2tf(rb[i].x); u.y = f2tf(rb[i].y);
                     u.z = f2tf(rb[i].z); u.w = f2tf(rb[i].w);
            *(uint4*)&Ab[n * 36 + kq] = u;
        }
        __syncthreads();
        if (c0 + 32 < C) {
            #pragma unroll
            for (int i = 0; i < 4; i++) {
                int idx = tid + 256 * i;
                int o = idx >> 3, kq = (idx & 7) * 4;
                ra[i] = *(const float4*)&W[(size_t)(o0 + o) * C + c0 + 32 + kq];
            }
            rb[0] = fused_pre_load(prow0, vb, bl0, c0 + 32 + bkq);
            rb[1] = fused_pre_load(prow1, vb, bl1, c0 + 32 + bkq);
        }
        #pragma unroll
        for (int ks = 0; ks < 4; ks++) {
            int kk = ks * 8 + tig;
            uint32_t aF[4];
            aF[0] = Wa[(wm + gid) * 36 + kk];
            aF[1] = Wa[(wm + gid + 8) * 36 + kk];
            aF[2] = Wa[(wm + gid) * 36 + kk + 4];
            aF[3] = Wa[(wm + gid + 8) * 36 + kk + 4];
            #pragma unroll
            for (int nt = 0; nt < 8; nt++) {
                uint32_t b0 = Ab[(nt * 8 + gid) * 36 + kk];
                uint32_t b1 = Ab[(nt * 8 + gid) * 36 + kk + 4];
                mma_tf32(Cacc[nt], aF, b0, b1);
            }
        }
        __syncthreads();
    }

    const int olo = o0 + wm + gid, ohi = olo + 8;
    const float sclo = scale[olo], bilo = bias[olo];
    const float schi = scale[ohi], bihi = bias[ohi];
    #pragma unroll
    for (int nt = 0; nt < 8; nt++) {
        int n = n0 + nt * 8 + 2 * tig;
        float2 lo, hi;
        lo.x = Cacc[nt][0] * sclo + bilo;
        lo.y = Cacc[nt][1] * sclo + bilo;
        hi.x = Cacc[nt][2] * schi + bihi;
        hi.y = Cacc[nt][3] * schi + bihi;
        *(float2*)&out[((size_t)b * O + olo) * Nsp + n] = lo;
        *(float2*)&out[((size_t)b * O + ohi) * Nsp + n] = hi;
    }
}

// =================================================================================
// attention v6: fp16 m16n8k16, log2-domain scores (q pre-scaled), ex2.f16x2 exp,
// row-sum l via ones-column MMA (zero extra LDS). cp.async double buffer.
// pool: [K0|K1 : 2x64x16] [V0|V1 : 2x32x36] words (17.4 KB).
// =================================================================================
#define KO(bf) ((bf) * 1024)
#define VO(bf) (2048 + (bf) * 1152)

__global__ __launch_bounds__(256) void k_attn_fp16(
    const uint32_t* __restrict__ qh, const uint32_t* __restrict__ kp,
    const uint32_t* __restrict__ vp, float* __restrict__ pre)
{
    __shared__ __align__(16) uint32_t pool[4352];

    const int bh = blockIdx.y;
    const int b = bh >> 3, h = bh & 7;
    const int tid = threadIdx.x;
    const int warp = tid >> 5, lane = tid & 31;
    const int gid = lane >> 2, tig = lane & 3;
    const int n0 = blockIdx.x * 128;

    // ---- stage q tile [128][16 words] (stride 17), build fp16 A-frags ----
    {
        const uint32_t* qb = qh + ((size_t)b * 4096 + n0) * 128 + h * 16;
        #pragma unroll
        for (int i = 0; i < 2; i++) {
            int idx = tid + 256 * i;
            int r = idx >> 2, seg = (idx & 3) * 4;
            uint4 t = *(const uint4*)&qb[(size_t)r * 128 + seg];
            pool[r * 17 + seg + 0] = t.x;
            pool[r * 17 + seg + 1] = t.y;
            pool[r * 17 + seg + 2] = t.z;
            pool[r * 17 + seg + 3] = t.w;
        }
    }
    __syncthreads();

    uint32_t qA[2][4];
    {
        int r0 = warp * 16 + gid;
        #pragma unroll
        for (int ks = 0; ks < 2; ks++) {
            int w = 8 * ks + tig;
            qA[ks][0] = pool[r0 * 17 + w];
            qA[ks][1] = pool[(r0 + 8) * 17 + w];
            qA[ks][2] = pool[r0 * 17 + w + 4];
            qA[ks][3] = pool[(r0 + 8) * 17 + w + 4];
        }
    }
    __syncthreads();

    const uint32_t* kpb = kp + ((size_t)b * 8 + h) * 1024 * 16;
    const uint32_t* vpb = vp + ((size_t)b * 8 + h) * 16 * 1024;

    // prefetch chunk 0
    {
        int rk = tid >> 2, sk = (tid & 3) * 4;
        uint32_t dK = (uint32_t)__cvta_generic_to_shared(&pool[KO(0) + rk * 16 + sk]);
        asm volatile("cp.async.cg.shared.global [%0], [%1], 16;"
                     :: "r"(dK), "l"(&kpb[(size_t)rk * 16 + sk]));
        int dv = tid >> 3, sv = (tid & 7) * 4;
        uint32_t dV = (uint32_t)__cvta_generic_to_shared(&pool[VO(0) + dv * 36 + sv]);
        asm volatile("cp.async.cg.shared.global [%0], [%1], 16;"
                     :: "r"(dV), "l"(&vpb[(size_t)dv * 32 + sv]));
    }
    asm volatile("cp.async.commit_group;" ::: "memory");

    float O[4][4];
    #pragma unroll
    for (int i = 0; i < 4; i++)
        #pragma unroll
        for (int j = 0; j < 4; j++) O[i][j] = 0.0f;
    float Lacc[4] = {0.f, 0.f, 0.f, 0.f};
    // ones-column B fragment (col 0 = 1.0h): only gid==0 lanes non-zero
    const uint32_t onesB = (gid == 0) ? 0x3C003C00u : 0u;

    for (int ci = 0; ci < 16; ci++) {
        const int cur = ci & 1;
        if (ci < 15) {
            int rk = tid >> 2, sk = (tid & 3) * 4;
            uint32_t dK = (uint32_t)__cvta_generic_to_shared(&pool[KO(cur ^ 1) + rk * 16 + sk]);
            asm volatile("cp.async.cg.shared.global [%0], [%1], 16;"
                         :: "r"(dK), "l"(&kpb[(size_t)((ci + 1) * 64 + rk) * 16 + sk]));
            int dv = tid >> 3, sv = (tid & 7) * 4;
            uint32_t dV = (uint32_t)__cvta_generic_to_shared(&pool[VO(cur ^ 1) + dv * 36 + sv]);
            asm volatile("cp.async.cg.shared.global [%0], [%1], 16;"
                         :: "r"(dV), "l"(&vpb[(size_t)(ci + 1) * 1024 + dv * 32 + sv]));
            asm volatile("cp.async.commit_group;" ::: "memory");
            asm volatile("cp.async.wait_group 1;" ::: "memory");
        } else {
            asm volatile("cp.async.wait_group 0;" ::: "memory");
        }
        __syncthreads();

        const uint32_t* Kc = &pool[KO(cur)];
        const uint32_t* Vc = &pool[VO(cur)];
        uint4 vr[4];
        #pragma unroll
        for (int g = 0; g < 4; g++) {
            // ---- QK (log2-domain scores; q pre-scaled) ----
            uint4 kwA = *(const uint4*)&Kc[((2 * g) * 8 + gid) * 16 + tig * 4];
            uint4 kwB = *(const uint4*)&Kc[((2 * g + 1) * 8 + gid) * 16 + tig * 4];
            float S0[4] = {0.f, 0.f, 0.f, 0.f};
            float S1[4] = {0.f, 0.f, 0.f, 0.f};
            mma_fp16(S0, qA[0], kwA.x, kwA.y);
            mma_fp16(S0, qA[1], kwA.z, kwA.w);
            mma_fp16(S1, qA[0], kwB.x, kwB.y);
            mma_fp16(S1, qA[1], kwB.z, kwB.w);
            // ---- p = 2^S, two at a time in fp16; C-frag IS the A-frag ----
            uint32_t pA[4];
            pA[0] = h2exp2(packh2(S0[0], S0[1]));
            pA[1] = h2exp2(packh2(S0[2], S0[3]));
            pA[2] = h2exp2(packh2(S1[0], S1[1]));
            pA[3] = h2exp2(packh2(S1[2], S1[3]));
            // ---- l via ones-column MMA (fp32 accumulate, same p as AV) ----
            mma_fp16(Lacc, pA, onesB, onesB);
            // ---- AV k16 step g ----
            if ((g & 1) == 0) {
                #pragma unroll
                for (int mt = 0; mt < 4; mt++)
                    vr[mt] = *(const uint4*)&Vc[(mt * 8 + gid) * 36 + tig * 8 + 2 * g];
                #pragma unroll
                for (int mt = 0; mt < 4; mt++)
                    mma_fp16(O[mt], pA, vr[mt].x, vr[mt].y);
            } else {
                #pragma unroll
                for (int mt = 0; mt < 4; mt++)
                    mma_fp16(O[mt], pA, vr[mt].z, vr[mt].w);
            }
        }
        __syncthreads();
    }

    // ---- l lives in col 0 (tig==0 lanes): broadcast within quad, normalize ----
    float l_lo = __shfl_sync(0xFFFFFFFFu, Lacc[0], lane & ~3);
    float l_hi = __shfl_sync(0xFFFFFFFFu, Lacc[2], lane & ~3);
    float inv_lo = 1.0f / l_lo;
    float inv_hi = 1.0f / l_hi;

    const int rlo = n0 + warp * 16 + gid;
    const int rhi = rlo + 8;
    #pragma unroll
    for (int mt = 0; mt < 4; mt++) {
        int c = h * 32 + mt * 8 + 2 * tig;
        float2 lo = make_float2(O[mt][0] * inv_lo, O[mt][1] * inv_lo);
        float2 hi = make_float2(O[mt][2] * inv_hi, O[mt][3] * inv_hi);
        *(float2*)&pre[((size_t)b * 4096 + rlo) * 256 + c] = lo;
        *(float2*)&pre[((size_t)b * 4096 + rhi) * 256 + c] = hi;
    }
}

// =================================================================================
// depthwise 7x7 conv (pad 3), planar v input -> g_vpe[b][m][c]
// =================================================================================
__global__ __launch_bounds__(256) void k_dwconv(
    const float* __restrict__ vt, const float* __restrict__ Wpe,
    const float* __restrict__ pe_scale, const float* __restrict__ pe_bias,
    float* __restrict__ vpe)
{
    __shared__ float plane[1024];
    __shared__ float wsm[49];
    const int c = blockIdx.x;
    const int b = blockIdx.y;
    const int tid = threadIdx.x;

    *(float4*)&plane[tid * 4] = *(const float4*)&vt[((size_t)b * 256 + c) * 1024 + tid * 4];
    if (tid < 49) wsm[tid] = Wpe[c * 49 + tid];
    __syncthreads();

    const float sc = pe_scale[c], bi = pe_bias[c];
    #pragma unroll
    for (int i = 0; i < 4; i++) {
        int m = tid + 256 * i;
        int y = m >> 5, x = m & 31;
        float s = 0.0f;
        #pragma unroll
        for (int ky = 0; ky < 7; ky++) {
            int iy = y + ky - 3;
            if ((unsigned)iy < 32u) {
                #pragma unroll
                for (int kx = 0; kx < 7; kx++) {
                    int ix = x + kx - 3;
                    if ((unsigned)ix < 32u) s += plane[iy * 32 + ix] * wsm[ky * 7 + kx];
                }
            }
        }
        vpe[((size_t)b * 1024 + m) * 256 + c] = s * sc + bi;
    }
}

// =================================================================================
// launch — kv-conv + dwconv chain overlapped on a second stream
// =================================================================================
extern "C" void kernel_launch(void* const* d_in, const int* in_sizes, int n_in,
                              void* d_out, int out_size)
{
    (void)in_sizes; (void)n_in; (void)out_size;
    const float* x          = (const float*)d_in[0];
    const float* upper_feat = (const float*)d_in[1];
    const float* Wq         = (const float*)d_in[2];
    const float* q_scale    = (const float*)d_in[3];
    const float* q_bias     = (const float*)d_in[4];
    const float* Wkv        = (const float*)d_in[5];
    const float* kv_scale   = (const float*)d_in[6];
    const float* kv_bias    = (const float*)d_in[7];
    const float* Wpe        = (const float*)d_in[8];
    const float* pe_scale   = (const float*)d_in[9];
    const float* pe_bias    = (const float*)d_in[10];
    const float* Wproj      = (const float*)d_in[11];
    const float* proj_scale = (const float*)d_in[12];
    const float* proj_bias  = (const float*)d_in[13];
    float* out = (float*)d_out;

    float *pvt, *pvpe, *ppre;
    uint32_t *pqh, *pkp, *pvp;
    cudaGetSymbolAddress((void**)&pqh,  g_qh);
    cudaGetSymbolAddress((void**)&pkp,  g_kp);
    cudaGetSymbolAddress((void**)&pvp,  g_vp);
    cudaGetSymbolAddress((void**)&pvt,  g_vt);
    cudaGetSymbolAddress((void**)&pvpe, g_vpe);
    cudaGetSymbolAddress((void**)&ppre, g_pre);

    static cudaStream_t s2 = nullptr;
    static cudaEvent_t e_fork = nullptr, e_kv = nullptr, e_dw = nullptr;
    if (s2 == nullptr) {
        cudaStreamCreateWithFlags(&s2, cudaStreamNonBlocking);
        cudaEventCreateWithFlags(&e_fork, cudaEventDisableTiming);
        cudaEventCreateWithFlags(&e_kv,   cudaEventDisableTiming);
        cudaEventCreateWithFlags(&e_dw,   cudaEventDisableTiming);
    }

    // fork
    cudaEventRecord(e_fork, 0);
    cudaStreamWaitEvent(s2, e_fork, 0);

    // stream 2: kv conv -> dwconv
    k_conv_tf32_nmajor<<<dim3(8, 8, 4), 256, 0, s2>>>(
        upper_feat, Wkv, kv_scale, kv_bias, nullptr, pkp, pvp, pvt, 256, 1024, 512);
    cudaEventRecord(e_kv, s2);
    k_dwconv<<<dim3(256, 4), 256, 0, s2>>>(pvt, Wpe, pe_scale, pe_bias, pvpe);
    cudaEventRecord(e_dw, s2);

    // main stream: q conv, then attention (needs kv)
    k_conv_tf32_nmajor<<<dim3(4, 32, 4), 256>>>(
        x, Wq, q_scale, q_bias, pqh, nullptr, nullptr, nullptr, 256, 4096, 256);
    cudaStreamWaitEvent(0, e_kv, 0);
    k_attn_fp16<<<dim3(32, 32), 256>>>(pqh, pkp, pvp, ppre);

    // join: proj needs attention (stream order) + dwconv (event); upsample fused
    cudaStreamWaitEvent(0, e_dw, 0);
    k_conv_tf32_proj<<<dim3(2, 64, 4), 256>>>(
        ppre, pvpe, Wproj, proj_scale, proj_bias, out, 256, 4096, 256);
}

// round 13
// speedup vs baseline: 1.9965x; 1.1614x over previous
#include <cuda_runtime.h>
#include <cuda_fp16.h>
#include <math.h>
#include <stdint.h>

// ---------------- scratch (static device globals; no allocation) ----------------
__device__ uint32_t g_qh [(size_t)4 * 4096 * 128];     // [b][n][128 half2]  q fp16 (pre-scaled)
__device__ uint32_t g_kp [(size_t)4 * 8 * 1024 * 16];  // [b][h][m][16 half2] K frag-perm
__device__ uint32_t g_vp [(size_t)4 * 8 * 16 * 1024];  // [b][h][ci][d][32 half2] V frag-perm
__device__ float    g_vt [(size_t)4 * 256 * 1024];     // [b][c][m] fp32 planar v
__device__ float    g_vpe[(size_t)4 * 1024 * 256];     // [b][m][c]
__device__ float    g_pre[(size_t)4 * 4096 * 256];     // [b][n][c]  attention output only

// ---------------- helpers ----------------
__device__ __forceinline__ void mma_fp16(float c[4], const uint32_t a[4],
                                         uint32_t b0, uint32_t b1) {
    asm("mma.sync.aligned.m16n8k16.row.col.f32.f16.f16.f32 "
        "{%0,%1,%2,%3}, {%4,%5,%6,%7}, {%8,%9}, {%0,%1,%2,%3};"
        : "+f"(c[0]), "+f"(c[1]), "+f"(c[2]), "+f"(c[3])
        : "r"(a[0]), "r"(a[1]), "r"(a[2]), "r"(a[3]), "r"(b0), "r"(b1));
}
__device__ __forceinline__ uint32_t packh2(float a, float b) {
    __half2 h = __floats2half2_rn(a, b);
    return *(uint32_t*)&h;
}
__device__ __forceinline__ uint32_t h2exp2(uint32_t x) {
    uint32_t r; asm("ex2.approx.f16x2 %0, %1;" : "=r"(r) : "r"(x)); return r;
}

// q pre-scale: 1/sqrt(32) * log2(e), folded so attention uses raw ex2
#define QPRESCALE ((float)(0.17677669529663687 * 1.4426950408889634))

// =================================================================================
// fp16 conv1x1, input planar [C][Nsp], tile 128n x 64o, pipelined loads.
// A smem [kw][m] stride 136 (k-pairs packed half2); W smem [o][kw] stride 20.
// q mode (qh!=null): fp16 half2 output, pre-multiplied by QPRESCALE.
// kv mode (kp!=null): K/V fragment-permuted fp16 buffers + fp32 planar v.
// =================================================================================
__global__ __launch_bounds__(256) void k_conv_fp16_nmajor(
    const float* __restrict__ X, const float* __restrict__ W,
    const float* __restrict__ scale, const float* __restrict__ bias,
    uint32_t* __restrict__ qh, uint32_t* __restrict__ kp, uint32_t* __restrict__ vp,
    float* __restrict__ vt, int C, int Nsp, int O)
{
    __shared__ __align__(16) uint32_t As[16 * 136];
    __shared__ __align__(16) uint32_t Ws[64 * 20];
    const int b  = blockIdx.z;
    const int n0 = blockIdx.y * 128;
    const int o0 = blockIdx.x * 64;
    const int tid = threadIdx.x;
    const int warp = tid >> 5, lane = tid & 31;
    const int gid = lane >> 2, tig = lane & 3;
    const int wm = warp * 16;

    const float* Xb = X + (size_t)b * C * Nsp;
    float Cacc[8][4];
    #pragma unroll
    for (int i = 0; i < 8; i++)
        #pragma unroll
        for (int j = 0; j < 4; j++) Cacc[i][j] = 0.0f;

    float4 ra[2][2], rb[2];
    // prefetch c0 = 0
    #pragma unroll
    for (int i = 0; i < 2; i++) {
        int idx = tid + 256 * i;
        int kw = idx >> 5, m4 = (idx & 31) * 4;
        ra[i][0] = *(const float4*)&Xb[(size_t)(2 * kw)     * Nsp + n0 + m4];
        ra[i][1] = *(const float4*)&Xb[(size_t)(2 * kw + 1) * Nsp + n0 + m4];
    }
    #pragma unroll
    for (int i = 0; i < 2; i++) {
        int idx = tid + 256 * i;
        int o = idx >> 3, kq = (idx & 7) * 4;
        rb[i] = *(const float4*)&W[(size_t)(o0 + o) * C + kq];
    }

    for (int c0 = 0; c0 < C; c0 += 32) {
        // stage current chunk (fp32 -> half2)
        #pragma unroll
        for (int i = 0; i < 2; i++) {
            int idx = tid + 256 * i;
            int kw = idx >> 5, m4 = (idx & 31) * 4;
            uint4 u;
            u.x = packh2(ra[i][0].x, ra[i][1].x);
            u.y = packh2(ra[i][0].y, ra[i][1].y);
            u.z = packh2(ra[i][0].z, ra[i][1].z);
            u.w = packh2(ra[i][0].w, ra[i][1].w);
            *(uint4*)&As[kw * 136 + m4] = u;
        }
        #pragma unroll
        for (int i = 0; i < 2; i++) {
            int idx = tid + 256 * i;
            int o = idx >> 3, kw0 = (idx & 7) * 2;
            uint2 v;
            v.x = packh2(rb[i].x, rb[i].y);
            v.y = packh2(rb[i].z, rb[i].w);
            *(uint2*)&Ws[o * 20 + kw0] = v;
        }
        __syncthreads();
        // prefetch next chunk
        if (c0 + 32 < C) {
            #pragma unroll
            for (int i = 0; i < 2; i++) {
                int idx = tid + 256 * i;
                int kw = idx >> 5, m4 = (idx & 31) * 4;
                ra[i][0] = *(const float4*)&Xb[(size_t)(c0 + 32 + 2 * kw)     * Nsp + n0 + m4];
                ra[i][1] = *(const float4*)&Xb[(size_t)(c0 + 32 + 2 * kw + 1) * Nsp + n0 + m4];
            }
            #pragma unroll
            for (int i = 0; i < 2; i++) {
                int idx = tid + 256 * i;
                int o = idx >> 3, kq = (idx & 7) * 4;
                rb[i] = *(const float4*)&W[(size_t)(o0 + o) * C + c0 + 32 + kq];
            }
        }
        #pragma unroll
        for (int ks = 0; ks < 2; ks++) {
            int kwb = ks * 8;
            uint32_t aF[4];
            aF[0] = As[(kwb + tig) * 136 + wm + gid];
            aF[1] = As[(kwb + tig) * 136 + wm + gid + 8];
            aF[2] = As[(kwb + tig + 4) * 136 + wm + gid];
            aF[3] = As[(kwb + tig + 4) * 136 + wm + gid + 8];
            #pragma unroll
            for (int nt = 0; nt < 8; nt++) {
                uint32_t b0 = Ws[(nt * 8 + gid) * 20 + kwb + tig];
                uint32_t b1 = Ws[(nt * 8 + gid) * 20 + kwb + tig + 4];
                mma_fp16(Cacc[nt], aF, b0, b1);
            }
        }
        __syncthreads();
    }

    const int nlo = n0 + wm + gid, nhi = nlo + 8;
    #pragma unroll
    for (int nt = 0; nt < 8; nt++) {
        int o = o0 + nt * 8 + 2 * tig;          // even channel
        float2 sc = *(const float2*)&scale[o];
        float2 bi = *(const float2*)&bias[o];
        float2 lo, hi;
        lo.x = Cacc[nt][0] * sc.x + bi.x;
        lo.y = Cacc[nt][1] * sc.y + bi.y;
        hi.x = Cacc[nt][2] * sc.x + bi.x;
        hi.y = Cacc[nt][3] * sc.y + bi.y;

        if (qh != nullptr) {
            qh[((size_t)b * Nsp + nlo) * (O >> 1) + (o >> 1)] =
                packh2(lo.x * QPRESCALE, lo.y * QPRESCALE);
            qh[((size_t)b * Nsp + nhi) * (O >> 1) + (o >> 1)] =
                packh2(hi.x * QPRESCALE, hi.y * QPRESCALE);
        } else {
            int h = o >> 6;
            int c = o & 63;
            if (c < 32) {
                int w = ((c & 7) >> 1) * 4 + (((c >> 3) & 1) | (((c >> 4) & 1) << 1));
                size_t base = ((size_t)b * 8 + h) * 1024;
                kp[(base + nlo) * 16 + w] = packh2(lo.x, lo.y);
                kp[(base + nhi) * 16 + w] = packh2(hi.x, hi.y);
            } else {
                int cv = c - 32;
                __half* vph = (__half*)vp;
                size_t bhb = ((size_t)b * 8 + h) * 16 * 1024 * 2;
                #pragma unroll
                for (int sel = 0; sel < 4; sel++) {
                    int m = (sel & 2) ? nhi : nlo;
                    int d = cv + (sel & 1);
                    float v = (sel == 0) ? lo.x : (sel == 1) ? lo.y : (sel == 2) ? hi.x : hi.y;
                    int ci = m >> 6, rm = m & 63;
                    int pr = rm >> 1, lb = rm & 1;
                    int pos = (pr & 3) * 8 + (pr >> 2);
                    vph[bhb + (((size_t)ci * 32 + d) * 32 + pos) * 2 + lb] = __float2half_rn(v);
                }
                int vc = h * 32 + cv;
                vt[((size_t)b * 256 + vc)     * Nsp + nlo] = lo.x;
                vt[((size_t)b * 256 + vc + 1) * Nsp + nlo] = lo.y;
                vt[((size_t)b * 256 + vc)     * Nsp + nhi] = hi.x;
                vt[((size_t)b * 256 + vc + 1) * Nsp + nhi] = hi.y;
            }
        }
    }
}

// =================================================================================
// bilerp descriptor for the fused upsample (coords depend only on spatial n)
// =================================================================================
struct Bil { int r00, r01, r10, r11; float w00, w01, w10, w11; };
__device__ __forceinline__ Bil make_bil(int n) {
    int y = n >> 6, x = n & 63;
    float ys = y * 0.5f - 0.25f;
    float xs = x * 0.5f - 0.25f;
    int y0 = (int)floorf(ys), x0 = (int)floorf(xs);
    float wy = ys - (float)y0, wx = xs - (float)x0;
    int y0c = max(y0, 0), y1c = min(y0 + 1, 31);
    int x0c = max(x0, 0), x1c = min(x0 + 1, 31);
    Bil bl;
    bl.r00 = y0c * 32 + x0c; bl.r01 = y0c * 32 + x1c;
    bl.r10 = y1c * 32 + x0c; bl.r11 = y1c * 32 + x1c;
    bl.w00 = (1.f - wy) * (1.f - wx); bl.w01 = (1.f - wy) * wx;
    bl.w10 = wy * (1.f - wx);         bl.w11 = wy * wx;
    return bl;
}
__device__ __forceinline__ float4 fused_pre_load(
    const float* __restrict__ pre_row, const float* __restrict__ vb,
    const Bil& bl, int cq)
{
    float4 t   = *(const float4*)&pre_row[cq];
    float4 v00 = *(const float4*)&vb[bl.r00 * 256 + cq];
    float4 v01 = *(const float4*)&vb[bl.r01 * 256 + cq];
    float4 v10 = *(const float4*)&vb[bl.r10 * 256 + cq];
    float4 v11 = *(const float4*)&vb[bl.r11 * 256 + cq];
    t.x += bl.w00 * v00.x + bl.w01 * v01.x + bl.w10 * v10.x + bl.w11 * v11.x;
    t.y += bl.w00 * v00.y + bl.w01 * v01.y + bl.w10 * v10.y + bl.w11 * v11.y;
    t.z += bl.w00 * v00.z + bl.w01 * v01.z + bl.w10 * v10.z + bl.w11 * v11.z;
    t.w += bl.w00 * v00.w + bl.w01 * v01.w + bl.w10 * v10.w + bl.w11 * v11.w;
    return t;
}

// =================================================================================
// fp16 conv1x1 projection with FUSED upsample+add on the B-tile input.
// A = W [128 o][kw] stride 20; B = (pre + bilerp(vpe)) [64 n][kw] stride 20.
// Output planar [O][Nsp].
// =================================================================================
__global__ __launch_bounds__(256) void k_conv_fp16_proj(
    const float* __restrict__ Ain, const float* __restrict__ vpe,
    const float* __restrict__ W,
    const float* __restrict__ scale, const float* __restrict__ bias,
    float* __restrict__ out, int C, int Nsp, int O)
{
    __shared__ __align__(16) uint32_t Wa[128 * 20];
    __shared__ __align__(16) uint32_t Ab[64 * 20];
    const int b  = blockIdx.z;
    const int o0 = blockIdx.x * 128;
    const int n0 = blockIdx.y * 64;
    const int tid = threadIdx.x;
    const int warp = tid >> 5, lane = tid & 31;
    const int gid = lane >> 2, tig = lane & 3;
    const int wm = warp * 16;

    const float* Ainb = Ain + (size_t)b * Nsp * C;
    const float* vb   = vpe + (size_t)b * 1024 * 256;

    const int bn0 = n0 + (tid >> 3);
    const int bn1 = n0 + ((tid + 256) >> 3);
    const Bil bl0 = make_bil(bn0);
    const Bil bl1 = make_bil(bn1);
    const float* prow0 = &Ainb[(size_t)bn0 * C];
    const float* prow1 = &Ainb[(size_t)bn1 * C];
    const int bkq = (tid & 7) * 4;

    float Cacc[8][4];
    #pragma unroll
    for (int i = 0; i < 8; i++)
        #pragma unroll
        for (int j = 0; j < 4; j++) Cacc[i][j] = 0.0f;

    float4 ra[4], rb[2];
    #pragma unroll
    for (int i = 0; i < 4; i++) {
        int idx = tid + 256 * i;
        int o = idx >> 3, kq = (idx & 7) * 4;
        ra[i] = *(const float4*)&W[(size_t)(o0 + o) * C + kq];
    }
    rb[0] = fused_pre_load(prow0, vb, bl0, bkq);
    rb[1] = fused_pre_load(prow1, vb, bl1, bkq);

    for (int c0 = 0; c0 < C; c0 += 32) {
        #pragma unroll
        for (int i = 0; i < 4; i++) {
            int idx = tid + 256 * i;
            int o = idx >> 3, kw0 = (idx & 7) * 2;
            uint2 v;
            v.x = packh2(ra[i].x, ra[i].y);
            v.y = packh2(ra[i].z, ra[i].w);
            *(uint2*)&Wa[o * 20 + kw0] = v;
        }
        #pragma unroll
        for (int i = 0; i < 2; i++) {
            int idx = tid + 256 * i;
            int n = idx >> 3, kw0 = (idx & 7) * 2;
            uint2 v;
            v.x = packh2(rb[i].x, rb[i].y);
            v.y = packh2(rb[i].z, rb[i].w);
            *(uint2*)&Ab[n * 20 + kw0] = v;
        }
        __syncthreads();
        if (c0 + 32 < C) {
            #pragma unroll
            for (int i = 0; i < 4; i++) {
                int idx = tid + 256 * i;
                int o = idx >> 3, kq = (idx & 7) * 4;
                ra[i] = *(const float4*)&W[(size_t)(o0 + o) * C + c0 + 32 + kq];
            }
            rb[0] = fused_pre_load(prow0, vb, bl0, c0 + 32 + bkq);
            rb[1] = fused_pre_load(prow1, vb, bl1, c0 + 32 + bkq);
        }
        #pragma unroll
        for (int ks = 0; ks < 2; ks++) {
            int kwb = ks * 8;
            uint32_t aF[4];
            aF[0] = Wa[(wm + gid) * 20 + kwb + tig];
            aF[1] = Wa[(wm + gid + 8) * 20 + kwb + tig];
            aF[2] = Wa[(wm + gid) * 20 + kwb + tig + 4];
            aF[3] = Wa[(wm + gid + 8) * 20 + kwb + tig + 4];
            #pragma unroll
            for (int nt = 0; nt < 8; nt++) {
                uint32_t b0 = Ab[(nt * 8 + gid) * 20 + kwb + tig];
                uint32_t b1 = Ab[(nt * 8 + gid) * 20 + kwb + tig + 4];
                mma_fp16(Cacc[nt], aF, b0, b1);
            }
        }
        __syncthreads();
    }

    const int olo = o0 + wm + gid, ohi = olo + 8;
    const float sclo = scale[olo], bilo = bias[olo];
    const float schi = scale[ohi], bihi = bias[ohi];
    #pragma unroll
    for (int nt = 0; nt < 8; nt++) {
        int n = n0 + nt * 8 + 2 * tig;
        float2 lo, hi;
        lo.x = Cacc[nt][0] * sclo + bilo;
        lo.y = Cacc[nt][1] * sclo + bilo;
        hi.x = Cacc[nt][2] * schi + bihi;
        hi.y = Cacc[nt][3] * schi + bihi;
        *(float2*)&out[((size_t)b * O + olo) * Nsp + n] = lo;
        *(float2*)&out[((size_t)b * O + ohi) * Nsp + n] = hi;
    }
}

// =================================================================================
// attention: fp16 m16n8k16, log2-domain scores, ex2.f16x2 exp, l via ones-MMA.
// (unchanged from R12 — proven)
// =================================================================================
#define KO(bf) ((bf) * 1024)
#define VO(bf) (2048 + (bf) * 1152)

__global__ __launch_bounds__(256) void k_attn_fp16(
    const uint32_t* __restrict__ qh, const uint32_t* __restrict__ kp,
    const uint32_t* __restrict__ vp, float* __restrict__ pre)
{
    __shared__ __align__(16) uint32_t pool[4352];

    const int bh = blockIdx.y;
    const int b = bh >> 3, h = bh & 7;
    const int tid = threadIdx.x;
    const int warp = tid >> 5, lane = tid & 31;
    const int gid = lane >> 2, tig = lane & 3;
    const int n0 = blockIdx.x * 128;

    {
        const uint32_t* qb = qh + ((size_t)b * 4096 + n0) * 128 + h * 16;
        #pragma unroll
        for (int i = 0; i < 2; i++) {
            int idx = tid + 256 * i;
            int r = idx >> 2, seg = (idx & 3) * 4;
            uint4 t = *(const uint4*)&qb[(size_t)r * 128 + seg];
            pool[r * 17 + seg + 0] = t.x;
            pool[r * 17 + seg + 1] = t.y;
            pool[r * 17 + seg + 2] = t.z;
            pool[r * 17 + seg + 3] = t.w;
        }
    }
    __syncthreads();

    uint32_t qA[2][4];
    {
        int r0 = warp * 16 + gid;
        #pragma unroll
        for (int ks = 0; ks < 2; ks++) {
            int w = 8 * ks + tig;
            qA[ks][0] = pool[r0 * 17 + w];
            qA[ks][1] = pool[(r0 + 8) * 17 + w];
            qA[ks][2] = pool[r0 * 17 + w + 4];
            qA[ks][3] = pool[(r0 + 8) * 17 + w + 4];
        }
    }
    __syncthreads();

    const uint32_t* kpb = kp + ((size_t)b * 8 + h) * 1024 * 16;
    const uint32_t* vpb = vp + ((size_t)b * 8 + h) * 16 * 1024;

    {
        int rk = tid >> 2, sk = (tid & 3) * 4;
        uint32_t dK = (uint32_t)__cvta_generic_to_shared(&pool[KO(0) + rk * 16 + sk]);
        asm volatile("cp.async.cg.shared.global [%0], [%1], 16;"
                     :: "r"(dK), "l"(&kpb[(size_t)rk * 16 + sk]));
        int dv = tid >> 3, sv = (tid & 7) * 4;
        uint32_t dV = (uint32_t)__cvta_generic_to_shared(&pool[VO(0) + dv * 36 + sv]);
        asm volatile("cp.async.cg.shared.global [%0], [%1], 16;"
                     :: "r"(dV), "l"(&vpb[(size_t)dv * 32 + sv]));
    }
    asm volatile("cp.async.commit_group;" ::: "memory");

    float O[4][4];
    #pragma unroll
    for (int i = 0; i < 4; i++)
        #pragma unroll
        for (int j = 0; j < 4; j++) O[i][j] = 0.0f;
    float Lacc[4] = {0.f, 0.f, 0.f, 0.f};
    const uint32_t onesB = (gid == 0) ? 0x3C003C00u : 0u;

    for (int ci = 0; ci < 16; ci++) {
        const int cur = ci & 1;
        if (ci < 15) {
            int rk = tid >> 2, sk = (tid & 3) * 4;
            uint32_t dK = (uint32_t)__cvta_generic_to_shared(&pool[KO(cur ^ 1) + rk * 16 + sk]);
            asm volatile("cp.async.cg.shared.global [%0], [%1], 16;"
                         :: "r"(dK), "l"(&kpb[(size_t)((ci + 1) * 64 + rk) * 16 + sk]));
            int dv = tid >> 3, sv = (tid & 7) * 4;
            uint32_t dV = (uint32_t)__cvta_generic_to_shared(&pool[VO(cur ^ 1) + dv * 36 + sv]);
            asm volatile("cp.async.cg.shared.global [%0], [%1], 16;"
                         :: "r"(dV), "l"(&vpb[(size_t)(ci + 1) * 1024 + dv * 32 + sv]));
            asm volatile("cp.async.commit_group;" ::: "memory");
            asm volatile("cp.async.wait_group 1;" ::: "memory");
        } else {
            asm volatile("cp.async.wait_group 0;" ::: "memory");
        }
        __syncthreads();

        const uint32_t* Kc = &pool[KO(cur)];
        const uint32_t* Vc = &pool[VO(cur)];
        uint4 vr[4];
        #pragma unroll
        for (int g = 0; g < 4; g++) {
            uint4 kwA = *(const uint4*)&Kc[((2 * g) * 8 + gid) * 16 + tig * 4];
            uint4 kwB = *(const uint4*)&Kc[((2 * g + 1) * 8 + gid) * 16 + tig * 4];
            float S0[4] = {0.f, 0.f, 0.f, 0.f};
            float S1[4] = {0.f, 0.f, 0.f, 0.f};
            mma_fp16(S0, qA[0], kwA.x, kwA.y);
            mma_fp16(S0, qA[1], kwA.z, kwA.w);
            mma_fp16(S1, qA[0], kwB.x, kwB.y);
            mma_fp16(S1, qA[1], kwB.z, kwB.w);
            uint32_t pA[4];
            pA[0] = h2exp2(packh2(S0[0], S0[1]));
            pA[1] = h2exp2(packh2(S0[2], S0[3]));
            pA[2] = h2exp2(packh2(S1[0], S1[1]));
            pA[3] = h2exp2(packh2(S1[2], S1[3]));
            mma_fp16(Lacc, pA, onesB, onesB);
            if ((g & 1) == 0) {
                #pragma unroll
                for (int mt = 0; mt < 4; mt++)
                    vr[mt] = *(const uint4*)&Vc[(mt * 8 + gid) * 36 + tig * 8 + 2 * g];
                #pragma unroll
                for (int mt = 0; mt < 4; mt++)
                    mma_fp16(O[mt], pA, vr[mt].x, vr[mt].y);
            } else {
                #pragma unroll
                for (int mt = 0; mt < 4; mt++)
                    mma_fp16(O[mt], pA, vr[mt].z, vr[mt].w);
            }
        }
        __syncthreads();
    }

    float l_lo = __shfl_sync(0xFFFFFFFFu, Lacc[0], lane & ~3);
    float l_hi = __shfl_sync(0xFFFFFFFFu, Lacc[2], lane & ~3);
    float inv_lo = 1.0f / l_lo;
    float inv_hi = 1.0f / l_hi;

    const int rlo = n0 + warp * 16 + gid;
    const int rhi = rlo + 8;
    #pragma unroll
    for (int mt = 0; mt < 4; mt++) {
        int c = h * 32 + mt * 8 + 2 * tig;
        float2 lo = make_float2(O[mt][0] * inv_lo, O[mt][1] * inv_lo);
        float2 hi = make_float2(O[mt][2] * inv_hi, O[mt][3] * inv_hi);
        *(float2*)&pre[((size_t)b * 4096 + rlo) * 256 + c] = lo;
        *(float2*)&pre[((size_t)b * 4096 + rhi) * 256 + c] = hi;
    }
}

// =================================================================================
// depthwise 7x7 conv (pad 3), planar v input -> g_vpe[b][m][c]
// =================================================================================
__global__ __launch_bounds__(256) void k_dwconv(
    const float* __restrict__ vt, const float* __restrict__ Wpe,
    const float* __restrict__ pe_scale, const float* __restrict__ pe_bias,
    float* __restrict__ vpe)
{
    __shared__ float plane[1024];
    __shared__ float wsm[49];
    const int c = blockIdx.x;
    const int b = blockIdx.y;
    const int tid = threadIdx.x;

    *(float4*)&plane[tid * 4] = *(const float4*)&vt[((size_t)b * 256 + c) * 1024 + tid * 4];
    if (tid < 49) wsm[tid] = Wpe[c * 49 + tid];
    __syncthreads();

    const float sc = pe_scale[c], bi = pe_bias[c];
    #pragma unroll
    for (int i = 0; i < 4; i++) {
        int m = tid + 256 * i;
        int y = m >> 5, x = m & 31;
        float s = 0.0f;
        #pragma unroll
        for (int ky = 0; ky < 7; ky++) {
            int iy = y + ky - 3;
            if ((unsigned)iy < 32u) {
                #pragma unroll
                for (int kx = 0; kx < 7; kx++) {
                    int ix = x + kx - 3;
                    if ((unsigned)ix < 32u) s += plane[iy * 32 + ix] * wsm[ky * 7 + kx];
                }
            }
        }
        vpe[((size_t)b * 1024 + m) * 256 + c] = s * sc + bi;
    }
}

// =================================================================================
// launch — kv-conv + dwconv chain overlapped on a second stream
// =================================================================================
extern "C" void kernel_launch(void* const* d_in, const int* in_sizes, int n_in,
                              void* d_out, int out_size)
{
    (void)in_sizes; (void)n_in; (void)out_size;
    const float* x          = (const float*)d_in[0];
    const float* upper_feat = (const float*)d_in[1];
    const float* Wq         = (const float*)d_in[2];
    const float* q_scale    = (const float*)d_in[3];
    const float* q_bias     = (const float*)d_in[4];
    const float* Wkv        = (const float*)d_in[5];
    const float* kv_scale   = (const float*)d_in[6];
    const float* kv_bias    = (const float*)d_in[7];
    const float* Wpe        = (const float*)d_in[8];
    const float* pe_scale   = (const float*)d_in[9];
    const float* pe_bias    = (const float*)d_in[10];
    const float* Wproj      = (const float*)d_in[11];
    const float* proj_scale = (const float*)d_in[12];
    const float* proj_bias  = (const float*)d_in[13];
    float* out = (float*)d_out;

    float *pvt, *pvpe, *ppre;
    uint32_t *pqh, *pkp, *pvp;
    cudaGetSymbolAddress((void**)&pqh,  g_qh);
    cudaGetSymbolAddress((void**)&pkp,  g_kp);
    cudaGetSymbolAddress((void**)&pvp,  g_vp);
    cudaGetSymbolAddress((void**)&pvt,  g_vt);
    cudaGetSymbolAddress((void**)&pvpe, g_vpe);
    cudaGetSymbolAddress((void**)&ppre, g_pre);

    static cudaStream_t s2 = nullptr;
    static cudaEvent_t e_fork = nullptr, e_kv = nullptr, e_dw = nullptr;
    if (s2 == nullptr) {
        cudaStreamCreateWithFlags(&s2, cudaStreamNonBlocking);
        cudaEventCreateWithFlags(&e_fork, cudaEventDisableTiming);
        cudaEventCreateWithFlags(&e_kv,   cudaEventDisableTiming);
        cudaEventCreateWithFlags(&e_dw,   cudaEventDisableTiming);
    }

    // fork
    cudaEventRecord(e_fork, 0);
    cudaStreamWaitEvent(s2, e_fork, 0);

    // stream 2: kv conv -> dwconv
    k_conv_fp16_nmajor<<<dim3(8, 8, 4), 256, 0, s2>>>(
        upper_feat, Wkv, kv_scale, kv_bias, nullptr, pkp, pvp, pvt, 256, 1024, 512);
    cudaEventRecord(e_kv, s2);
    k_dwconv<<<dim3(256, 4), 256, 0, s2>>>(pvt, Wpe, pe_scale, pe_bias, pvpe);
    cudaEventRecord(e_dw, s2);

    // main stream: q conv, then attention (needs kv)
    k_conv_fp16_nmajor<<<dim3(4, 32, 4), 256>>>(
        x, Wq, q_scale, q_bias, pqh, nullptr, nullptr, nullptr, 256, 4096, 256);
    cudaStreamWaitEvent(0, e_kv, 0);
    k_attn_fp16<<<dim3(32, 32), 256>>>(pqh, pkp, pvp, ppre);

    // join: proj needs attention (stream order) + dwconv (event); upsample fused
    cudaStreamWaitEvent(0, e_dw, 0);
    k_conv_fp16_proj<<<dim3(2, 64, 4), 256>>>(
        ppre, pvpe, Wproj, proj_scale, proj_bias, out, 256, 4096, 256);
}